// round 1
// baseline (speedup 1.0000x reference)
#include <cuda_runtime.h>
#include <math.h>

// Problem constants
#define D   512
#define QN  16
#define NT  4096   // B*L tokens
#define NG  512    // N gathered groups
#define PP  64     // group size P

#define SCALE 0.04419417382415922f  // 1/sqrt(512)

// Scratch (allocation-free: __device__ globals)
__device__ float g_Vp[NT * D];      // patch @ Wv + bv          [4096,512]
__device__ float g_sp[NT * QN];     // scaled patch scores      [4096,16]
__device__ float g_VQ[QN * D];      // Q0 @ Wv + bv             [16,512]
__device__ float g_Ak[QN * D];      // (Wk @ Q0^T)^T            [16,512]
__device__ float g_sself[QN];       // self-token scores        [16]
__device__ float g_qbk[QN];         // Q0[q] . bk               [16]

// ---------------------------------------------------------------------------
// k_pre: grid (16, 2), block 512.
//  y==0: VQ[q][t] = bv[t] + sum_d Q0[q,d] * Wv[d,t]   (coalesced over t)
//  y==1: Ak[q][t] = sum_d' Wk[t,d'] * Q0[q,d']        (each thread streams a row)
// ---------------------------------------------------------------------------
__global__ void k_pre(const float* __restrict__ query, const float* __restrict__ Wk,
                      const float* __restrict__ Wv, const float* __restrict__ bv) {
    __shared__ float q0[D];
    int q = blockIdx.x;
    int t = threadIdx.x;
    q0[t] = query[q * D + t];
    __syncthreads();
    if (blockIdx.y == 0) {
        float a0 = bv[t], a1 = 0.f;
#pragma unroll 8
        for (int d = 0; d < D; d += 2) {
            a0 += q0[d]     * Wv[d * D + t];
            a1 += q0[d + 1] * Wv[(d + 1) * D + t];
        }
        g_VQ[q * D + t] = a0 + a1;
    } else {
        const float4* wr = reinterpret_cast<const float4*>(Wk + (size_t)t * D);
        float a0 = 0.f, a1 = 0.f;
#pragma unroll 8
        for (int i = 0; i < D / 8; i++) {
            float4 w0 = wr[2 * i], w1 = wr[2 * i + 1];
            a0 += w0.x * q0[8*i+0] + w0.y * q0[8*i+1] + w0.z * q0[8*i+2] + w0.w * q0[8*i+3];
            a1 += w1.x * q0[8*i+4] + w1.y * q0[8*i+5] + w1.z * q0[8*i+6] + w1.w * q0[8*i+7];
        }
        g_Ak[q * D + t] = a0 + a1;
    }
}

// ---------------------------------------------------------------------------
// k_self: 1 block, 512 threads (16 warps). Warp q:
//   s_self[q] = (Q0[q].Ak[q] + Q0[q].bk) * scale ;  qbk[q] = Q0[q].bk
// ---------------------------------------------------------------------------
__global__ void k_self(const float* __restrict__ query, const float* __restrict__ bk) {
    int q = threadIdx.x >> 5, lane = threadIdx.x & 31;
    float s = 0.f, sb = 0.f;
#pragma unroll
    for (int d = lane; d < D; d += 32) {
        float qv = query[q * D + d];
        s  += qv * g_Ak[q * D + d];
        sb += qv * bk[d];
    }
#pragma unroll
    for (int o = 16; o; o >>= 1) {
        s  += __shfl_xor_sync(0xffffffffu, s, o);
        sb += __shfl_xor_sync(0xffffffffu, sb, o);
    }
    if (lane == 0) {
        g_qbk[q] = sb;
        g_sself[q] = (s + sb) * SCALE;
    }
}

// ---------------------------------------------------------------------------
// k_sp: grid 256, block 512 (16 warps). Block handles 16 token rows.
//   sp[t][q] = (patch[t].Ak[q] + qbk[q]) * scale
// Ak staged in smem (32KB); warp w owns row (row0+w) read straight from gmem.
// ---------------------------------------------------------------------------
__global__ void k_sp(const float* __restrict__ patch) {
    __shared__ float Aks[QN * D];
    __shared__ float qb[QN];
    int t = threadIdx.x;
    float4* As4 = reinterpret_cast<float4*>(Aks);
    const float4* g4 = reinterpret_cast<const float4*>(g_Ak);
#pragma unroll
    for (int i = 0; i < 4; i++) As4[t + i * 512] = g4[t + i * 512];
    if (t < QN) qb[t] = g_qbk[t];
    __syncthreads();

    int w = t >> 5, lane = t & 31;
    int row = blockIdx.x * 16 + w;
    const float* pr = patch + (size_t)row * D;
    float acc[QN];
#pragma unroll
    for (int q = 0; q < QN; q++) acc[q] = 0.f;
#pragma unroll
    for (int c = 0; c < D / 32; c++) {
        float pv = pr[lane + c * 32];
#pragma unroll
        for (int q = 0; q < QN; q++) acc[q] += pv * Aks[q * D + lane + c * 32];
    }
#pragma unroll
    for (int q = 0; q < QN; q++) {
        float v = acc[q];
#pragma unroll
        for (int o = 16; o; o >>= 1) v += __shfl_xor_sync(0xffffffffu, v, o);
        if (lane == 0) g_sp[row * QN + q] = (v + qb[q]) * SCALE;
    }
}

// ---------------------------------------------------------------------------
// k_gemm: Vp = patch @ Wv + bv.  [4096,512]x[512,512]
// BM=64, BN=64, BK=16, 128 threads, each thread 8x4 outputs.
// grid (512/64, 4096/64) = (8, 64) = 512 blocks -> all resident, FMA-bound.
// ---------------------------------------------------------------------------
#define BM 64
#define BN 64
#define BK 16
__global__ __launch_bounds__(128) void k_gemm(const float* __restrict__ patch,
                                              const float* __restrict__ Wv,
                                              const float* __restrict__ bv) {
    __shared__ float As[BK][BM + 4];  // transposed A tile, padded
    __shared__ float Bs[BK][BN + 4];
    int t = threadIdx.x;
    int m0 = blockIdx.y * BM, n0 = blockIdx.x * BN;
    int tx = t & 15, ty = t >> 4;     // tx: 16 col-groups of 4, ty: 8 row-groups of 8
    float acc[8][4];
#pragma unroll
    for (int i = 0; i < 8; i++)
#pragma unroll
        for (int j = 0; j < 4; j++) acc[i][j] = 0.f;

    for (int k0 = 0; k0 < D; k0 += BK) {
        // A tile: 64 rows x 16 cols = 256 float4, 2 per thread
#pragma unroll
        for (int i = 0; i < 2; i++) {
            int f = t + i * 128;
            int r = f >> 2, cg = f & 3;
            float4 v = *reinterpret_cast<const float4*>(patch + (size_t)(m0 + r) * D + k0 + cg * 4);
            As[cg * 4 + 0][r] = v.x; As[cg * 4 + 1][r] = v.y;
            As[cg * 4 + 2][r] = v.z; As[cg * 4 + 3][r] = v.w;
        }
        // B tile: 16 rows x 64 cols = 256 float4, 2 per thread
#pragma unroll
        for (int i = 0; i < 2; i++) {
            int f = t + i * 128;
            int r = f >> 4, cg = f & 15;
            float4 v = *reinterpret_cast<const float4*>(Wv + (size_t)(k0 + r) * D + n0 + cg * 4);
            *reinterpret_cast<float4*>(&Bs[r][cg * 4]) = v;
        }
        __syncthreads();
#pragma unroll
        for (int k = 0; k < BK; k++) {
            float4 a0 = *reinterpret_cast<const float4*>(&As[k][ty * 8]);
            float4 a1 = *reinterpret_cast<const float4*>(&As[k][ty * 8 + 4]);
            float4 b0 = *reinterpret_cast<const float4*>(&Bs[k][tx * 4]);
            float a[8] = {a0.x, a0.y, a0.z, a0.w, a1.x, a1.y, a1.z, a1.w};
            float b[4] = {b0.x, b0.y, b0.z, b0.w};
#pragma unroll
            for (int i = 0; i < 8; i++)
#pragma unroll
                for (int j = 0; j < 4; j++) acc[i][j] += a[i] * b[j];
        }
        __syncthreads();
    }
#pragma unroll
    for (int i = 0; i < 8; i++) {
        int m = m0 + ty * 8 + i;
#pragma unroll
        for (int j = 0; j < 4; j++) {
            int n = n0 + tx * 4 + j;
            g_Vp[(size_t)m * D + n] = acc[i][j] + bv[n];
        }
    }
}

// ---------------------------------------------------------------------------
// k_combine: one block per group n (512 blocks, 128 threads, float4 over d).
//  - build masked scores [16][65] (entry 0 = self), softmax per q
//  - patch_token[q][d] = w0*VQ + sum_p w[p] * Vp[idx[p]][d]  (regs: 16 x float4)
//  - fusion pooling over q, write out[n]
// ---------------------------------------------------------------------------
__global__ __launch_bounds__(128) void k_combine(const int* __restrict__ indices,
                                                 const unsigned* __restrict__ mask,
                                                 const float* __restrict__ Wf,
                                                 const float* __restrict__ bf,
                                                 float* __restrict__ out) {
    __shared__ float swS[QN][66];                  // raw scores, row per q
    __shared__ __align__(16) float swT[PP + 1][QN]; // normalized weights, row per slot
    __shared__ int sidx[PP];
    __shared__ unsigned smk[PP];
    __shared__ float red[QN][4];
    int n = blockIdx.x, t = threadIdx.x;
    int lane = t & 31, w = t >> 5;

    if (t < PP) {
        sidx[t] = indices[n * PP + t];
        smk[t]  = mask[n * PP + t];
    }
    __syncthreads();

    // Phase A: scores. 128 threads cover 64 p x 2 q-halves (8 q each).
    {
        int p = t & 63, half = t >> 6;
        int idx = sidx[p];
        const float NINF = __int_as_float(0xff800000u);
        float4 v0, v1;
        if (smk[p] != 0u) {
            const float4* sp4 = reinterpret_cast<const float4*>(g_sp + (size_t)idx * QN + half * 8);
            v0 = sp4[0]; v1 = sp4[1];
        } else {
            v0 = make_float4(NINF, NINF, NINF, NINF);
            v1 = v0;
        }
        int q0 = half * 8;
        swS[q0 + 0][p + 1] = v0.x; swS[q0 + 1][p + 1] = v0.y;
        swS[q0 + 2][p + 1] = v0.z; swS[q0 + 3][p + 1] = v0.w;
        swS[q0 + 4][p + 1] = v1.x; swS[q0 + 5][p + 1] = v1.y;
        swS[q0 + 6][p + 1] = v1.z; swS[q0 + 7][p + 1] = v1.w;
    }
    if (t < QN) swS[t][0] = g_sself[t];
    __syncthreads();

    // Phase B: softmax over 65 slots per q. Warp w handles q = w*4 .. w*4+3.
    {
        const float NINF = __int_as_float(0xff800000u);
#pragma unroll
        for (int qi = 0; qi < 4; qi++) {
            int q = w * 4 + qi;
            float v0 = swS[q][lane], v1 = swS[q][lane + 32];
            float v2 = (lane == 0) ? swS[q][64] : NINF;
            float mx = fmaxf(fmaxf(v0, v1), v2);
#pragma unroll
            for (int o = 16; o; o >>= 1) mx = fmaxf(mx, __shfl_xor_sync(0xffffffffu, mx, o));
            float e0 = expf(v0 - mx), e1 = expf(v1 - mx);
            float e2 = (lane == 0) ? expf(v2 - mx) : 0.f;
            float s = e0 + e1 + e2;
#pragma unroll
            for (int o = 16; o; o >>= 1) s += __shfl_xor_sync(0xffffffffu, s, o);
            float inv = 1.f / s;
            swT[lane][q] = e0 * inv;
            swT[lane + 32][q] = e1 * inv;
            if (lane == 0) swT[64][q] = e2 * inv;
        }
    }
    __syncthreads();

    // Phase C: accumulate patch_token in registers (16 x float4 per thread).
    float4 acc[QN];
    {
        const float4* VQ4 = reinterpret_cast<const float4*>(g_VQ);
        const float* w0row = swT[0];
#pragma unroll
        for (int q = 0; q < QN; q++) {
            float w0 = w0row[q];
            float4 vq = VQ4[q * 128 + t];
            acc[q] = make_float4(w0 * vq.x, w0 * vq.y, w0 * vq.z, w0 * vq.w);
        }
    }
#pragma unroll 4
    for (int p = 0; p < PP; p++) {
        float4 v = reinterpret_cast<const float4*>(g_Vp)[(size_t)sidx[p] * 128 + t];
        const float4* wrow = reinterpret_cast<const float4*>(swT[p + 1]);
        float4 w0v = wrow[0], w1v = wrow[1], w2v = wrow[2], w3v = wrow[3];
        const float wq[QN] = {w0v.x, w0v.y, w0v.z, w0v.w, w1v.x, w1v.y, w1v.z, w1v.w,
                              w2v.x, w2v.y, w2v.z, w2v.w, w3v.x, w3v.y, w3v.z, w3v.w};
#pragma unroll
        for (int q = 0; q < QN; q++) {
            acc[q].x += wq[q] * v.x; acc[q].y += wq[q] * v.y;
            acc[q].z += wq[q] * v.z; acc[q].w += wq[q] * v.w;
        }
    }

    // Phase D: fusion pooling.  f[q] = sum_d token[q][d]*Wf[d] + bf
    {
        float4 wf = reinterpret_cast<const float4*>(Wf)[t];
#pragma unroll
        for (int q = 0; q < QN; q++) {
            float fp = acc[q].x * wf.x + acc[q].y * wf.y + acc[q].z * wf.z + acc[q].w * wf.w;
#pragma unroll
            for (int o = 16; o; o >>= 1) fp += __shfl_xor_sync(0xffffffffu, fp, o);
            if (lane == 0) red[q][w] = fp;
        }
    }
    __syncthreads();
    {
        float bf0 = bf[0];
        float fv[QN], mx = -3.4e38f;
#pragma unroll
        for (int q = 0; q < QN; q++) {
            fv[q] = red[q][0] + red[q][1] + red[q][2] + red[q][3] + bf0;
            mx = fmaxf(mx, fv[q]);
        }
        float s = 0.f;
#pragma unroll
        for (int q = 0; q < QN; q++) { fv[q] = expf(fv[q] - mx); s += fv[q]; }
        float inv = 1.f / s;
        float4 o = make_float4(0.f, 0.f, 0.f, 0.f);
#pragma unroll
        for (int q = 0; q < QN; q++) {
            float g = fv[q] * inv;
            o.x += g * acc[q].x; o.y += g * acc[q].y;
            o.z += g * acc[q].z; o.w += g * acc[q].w;
        }
        reinterpret_cast<float4*>(out)[(size_t)n * 128 + t] = o;
    }
}

// ---------------------------------------------------------------------------
extern "C" void kernel_launch(void* const* d_in, const int* in_sizes, int n_in,
                              void* d_out, int out_size) {
    (void)in_sizes; (void)n_in; (void)out_size;
    const float* patch   = (const float*)d_in[0];
    const float* query   = (const float*)d_in[1];
    const float* Wk      = (const float*)d_in[2];
    const float* bk      = (const float*)d_in[3];
    const float* Wv      = (const float*)d_in[4];
    const float* bv      = (const float*)d_in[5];
    const float* Wf      = (const float*)d_in[6];
    const float* bf      = (const float*)d_in[7];
    const int* indices   = (const int*)d_in[8];
    const unsigned* mask = (const unsigned*)d_in[9];
    float* out           = (float*)d_out;

    k_pre<<<dim3(QN, 2), D>>>(query, Wk, Wv, bv);
    k_self<<<1, D>>>(query, bk);
    k_sp<<<NT / 16, D>>>(patch);
    k_gemm<<<dim3(D / BN, NT / BM), 128>>>(patch, Wv, bv);
    k_combine<<<NG, 128>>>(indices, mask, Wf, bf, out);
}

// round 3
// speedup vs baseline: 1.0497x; 1.0497x over previous
#include <cuda_runtime.h>
#include <math.h>

// Problem constants
#define D   512
#define QN  16
#define NT  4096   // B*L tokens
#define NG  512    // N gathered groups
#define PP  64     // group size P

#define SCALE 0.04419417382415922f  // 1/sqrt(512)

typedef unsigned long long ull;

// Scratch (allocation-free: __device__ globals)
__device__ float g_Vp[NT * D];      // patch @ Wv + bv          [4096,512]
__device__ float g_sp[NT * QN];     // scaled patch scores      [4096,16]
__device__ float g_VQ[QN * D];      // Q0 @ Wv + bv             [16,512]
__device__ float g_Ak[QN * D];      // (Wk @ Q0^T)^T            [16,512]
__device__ float g_pf[NT];          // Vp @ Wf                  [4096]
__device__ float g_tq[QN];          // VQ @ Wf                  [16]
__device__ float g_sself[QN];       // self-token scores        [16]
__device__ float g_qbk[QN];         // Q0[q] . bk               [16]

// ---- packed f32x2 helpers ------------------------------------------------
__device__ __forceinline__ ull dup2(float x) {
    ull r; unsigned xi = __float_as_uint(x);
    asm("mov.b64 %0, {%1, %1};" : "=l"(r) : "r"(xi));
    return r;
}
__device__ __forceinline__ void fma2(ull& d, ull a, ull b) {
    asm("fma.rn.f32x2 %0, %1, %2, %0;" : "+l"(d) : "l"(a), "l"(b));
}
__device__ __forceinline__ ull add2(ull a, ull b) {
    ull r; asm("add.rn.f32x2 %0, %1, %2;" : "=l"(r) : "l"(a), "l"(b));
    return r;
}
union F4U { float4 v; ull u[2]; };

// ---------------------------------------------------------------------------
// k_pre: grid (16, 2), block 512.
//  y==0: VQ[q][t] = bv[t] + sum_d Q0[q,d] * Wv[d,t]
//  y==1: Ak[q][t] = sum_d' Wk[t,d'] * Q0[q,d']
// ---------------------------------------------------------------------------
__global__ void k_pre(const float* __restrict__ query, const float* __restrict__ Wk,
                      const float* __restrict__ Wv, const float* __restrict__ bv) {
    __shared__ float q0[D];
    int q = blockIdx.x;
    int t = threadIdx.x;
    q0[t] = query[q * D + t];
    __syncthreads();
    if (blockIdx.y == 0) {
        float a0 = bv[t], a1 = 0.f;
#pragma unroll 8
        for (int d = 0; d < D; d += 2) {
            a0 += q0[d]     * Wv[d * D + t];
            a1 += q0[d + 1] * Wv[(d + 1) * D + t];
        }
        g_VQ[q * D + t] = a0 + a1;
    } else {
        const float4* wr = reinterpret_cast<const float4*>(Wk + (size_t)t * D);
        float a0 = 0.f, a1 = 0.f;
#pragma unroll 8
        for (int i = 0; i < D / 8; i++) {
            float4 w0 = wr[2 * i], w1 = wr[2 * i + 1];
            a0 += w0.x * q0[8*i+0] + w0.y * q0[8*i+1] + w0.z * q0[8*i+2] + w0.w * q0[8*i+3];
            a1 += w1.x * q0[8*i+4] + w1.y * q0[8*i+5] + w1.z * q0[8*i+6] + w1.w * q0[8*i+7];
        }
        g_Ak[q * D + t] = a0 + a1;
    }
}

// ---------------------------------------------------------------------------
// k_self: 1 block, 512 threads (16 warps). Warp q:
//   s_self[q], qbk[q], and tq[q] = VQ[q] . Wf
// ---------------------------------------------------------------------------
__global__ void k_self(const float* __restrict__ query, const float* __restrict__ bk,
                       const float* __restrict__ Wf) {
    int q = threadIdx.x >> 5, lane = threadIdx.x & 31;
    float s = 0.f, sb = 0.f, tv = 0.f;
#pragma unroll
    for (int d = lane; d < D; d += 32) {
        float qv = query[q * D + d];
        s  += qv * g_Ak[q * D + d];
        sb += qv * bk[d];
        tv += g_VQ[q * D + d] * Wf[d];
    }
#pragma unroll
    for (int o = 16; o; o >>= 1) {
        s  += __shfl_xor_sync(0xffffffffu, s, o);
        sb += __shfl_xor_sync(0xffffffffu, sb, o);
        tv += __shfl_xor_sync(0xffffffffu, tv, o);
    }
    if (lane == 0) {
        g_qbk[q] = sb;
        g_sself[q] = (s + sb) * SCALE;
        g_tq[q] = tv;
    }
}

// ---------------------------------------------------------------------------
// k_sp: grid 256, block 512 (16 warps). Block handles 16 token rows.
//   sp[t][q] = (patch[t].Ak[q] + qbk[q]) * scale
// ---------------------------------------------------------------------------
__global__ void k_sp(const float* __restrict__ patch) {
    __shared__ float Aks[QN * D];
    __shared__ float qb[QN];
    int t = threadIdx.x;
    float4* As4 = reinterpret_cast<float4*>(Aks);
    const float4* g4 = reinterpret_cast<const float4*>(g_Ak);
#pragma unroll
    for (int i = 0; i < 4; i++) As4[t + i * 512] = g4[t + i * 512];
    if (t < QN) qb[t] = g_qbk[t];
    __syncthreads();

    int w = t >> 5, lane = t & 31;
    int row = blockIdx.x * 16 + w;
    const float* pr = patch + (size_t)row * D;
    float acc[QN];
#pragma unroll
    for (int q = 0; q < QN; q++) acc[q] = 0.f;
#pragma unroll
    for (int c = 0; c < D / 32; c++) {
        float pv = pr[lane + c * 32];
#pragma unroll
        for (int q = 0; q < QN; q++) acc[q] += pv * Aks[q * D + lane + c * 32];
    }
#pragma unroll
    for (int q = 0; q < QN; q++) {
        float v = acc[q];
#pragma unroll
        for (int o = 16; o; o >>= 1) v += __shfl_xor_sync(0xffffffffu, v, o);
        if (lane == 0) g_sp[row * QN + q] = (v + qb[q]) * SCALE;
    }
}

// ---------------------------------------------------------------------------
// k_gemm: Vp = patch @ Wv + bv.  [4096,512]x[512,512]
// BM=64, BN=64, BK=16, 64 threads, each thread 8 rows x 8 cols, packed f32x2
// accumulators over column pairs (fma.rn.f32x2 -> 2x fp32 MAC throughput).
// ---------------------------------------------------------------------------
#define BM 64
#define BN 64
#define BK 16
__global__ __launch_bounds__(64) void k_gemm(const float* __restrict__ patch,
                                             const float* __restrict__ Wv,
                                             const float* __restrict__ bv) {
    __shared__ float As[BK][BM + 4];  // As[k][m]
    __shared__ float Bs[BK][BN + 4];  // Bs[k][n]
    int t = threadIdx.x;
    int m0 = blockIdx.y * BM, n0 = blockIdx.x * BN;
    int tx = t & 7, ty = t >> 3;      // cols n0+tx*8..+8, rows m0+ty*8..+8
    ull acc[8][4];
#pragma unroll
    for (int i = 0; i < 8; i++)
#pragma unroll
        for (int j = 0; j < 4; j++) acc[i][j] = 0ull;

    for (int k0 = 0; k0 < D; k0 += BK) {
        // A tile: 64 rows x 16 k = 256 float4; 4 per thread (transpose into As)
#pragma unroll
        for (int i = 0; i < 4; i++) {
            int f = t + i * 64;
            int r = f >> 2, cg = f & 3;
            float4 v = *reinterpret_cast<const float4*>(patch + (size_t)(m0 + r) * D + k0 + cg * 4);
            As[cg * 4 + 0][r] = v.x; As[cg * 4 + 1][r] = v.y;
            As[cg * 4 + 2][r] = v.z; As[cg * 4 + 3][r] = v.w;
        }
        // B tile: 16 k x 64 n = 256 float4; 4 per thread
#pragma unroll
        for (int i = 0; i < 4; i++) {
            int f = t + i * 64;
            int r = f >> 4, cg = f & 15;
            float4 v = *reinterpret_cast<const float4*>(Wv + (size_t)(k0 + r) * D + n0 + cg * 4);
            *reinterpret_cast<float4*>(&Bs[r][cg * 4]) = v;
        }
        __syncthreads();
#pragma unroll
        for (int k = 0; k < BK; k++) {
            float4 a0 = *reinterpret_cast<const float4*>(&As[k][ty * 8]);
            float4 a1 = *reinterpret_cast<const float4*>(&As[k][ty * 8 + 4]);
            F4U b0, b1;
            b0.v = *reinterpret_cast<const float4*>(&Bs[k][tx * 8]);
            b1.v = *reinterpret_cast<const float4*>(&Bs[k][tx * 8 + 4]);
            ull pb[4] = {b0.u[0], b0.u[1], b1.u[0], b1.u[1]};
            float av[8] = {a0.x, a0.y, a0.z, a0.w, a1.x, a1.y, a1.z, a1.w};
#pragma unroll
            for (int i = 0; i < 8; i++) {
                ull da = dup2(av[i]);
#pragma unroll
                for (int j = 0; j < 4; j++) fma2(acc[i][j], da, pb[j]);
            }
        }
        __syncthreads();
    }
    // epilogue: add bias (packed), STG.128
    ull bvp[4];
#pragma unroll
    for (int j = 0; j < 4; j++)
        bvp[j] = *reinterpret_cast<const ull*>(bv + n0 + tx * 8 + j * 2);
#pragma unroll
    for (int i = 0; i < 8; i++) {
        int m = m0 + ty * 8 + i;
        ull r0 = add2(acc[i][0], bvp[0]);
        ull r1 = add2(acc[i][1], bvp[1]);
        ull r2 = add2(acc[i][2], bvp[2]);
        ull r3 = add2(acc[i][3], bvp[3]);
        ulonglong2 s0; s0.x = r0; s0.y = r1;
        ulonglong2 s1; s1.x = r2; s1.y = r3;
        *reinterpret_cast<ulonglong2*>(&g_Vp[(size_t)m * D + n0 + tx * 8]) = s0;
        *reinterpret_cast<ulonglong2*>(&g_Vp[(size_t)m * D + n0 + tx * 8 + 4]) = s1;
    }
}

// ---------------------------------------------------------------------------
// k_pf: pf[t] = Vp[t] . Wf.  grid 512, block 256 (8 warps -> 8 rows/block).
// ---------------------------------------------------------------------------
__global__ __launch_bounds__(256) void k_pf(const float* __restrict__ Wf) {
    int row = blockIdx.x * 8 + (threadIdx.x >> 5);
    int lane = threadIdx.x & 31;
    float s = 0.f;
#pragma unroll
    for (int i = 0; i < D / 32; i++)
        s += g_Vp[(size_t)row * D + lane + i * 32] * Wf[lane + i * 32];
#pragma unroll
    for (int o = 16; o; o >>= 1) s += __shfl_xor_sync(0xffffffffu, s, o);
    if (lane == 0) g_pf[row] = s;
}

// ---------------------------------------------------------------------------
// k_combine: one block per group n (512 blocks, 128 threads).
// Algebraic collapse: out[d] = sum_q c0[q]*VQ[q,d] + sum_p e[p]*Vp[idx_p,d]
//   with c[q] = fw[q]/sum_q, e[p] = sum_q c[q]*w_unnorm[q,p].
// Only 1 effective weight per gathered row -> L2-gather bound.
// ---------------------------------------------------------------------------
__global__ __launch_bounds__(128) void k_combine(const int* __restrict__ indices,
                                                 const unsigned* __restrict__ mask,
                                                 const float* __restrict__ bf,
                                                 float* __restrict__ out) {
    __shared__ float S[QN][72];       // col 0 = self, cols 1..64 = p (unnorm exp)
    __shared__ int sidx[PP];
    __shared__ unsigned smk[PP];
    __shared__ float pfs[PP];
    __shared__ float tqs[QN];
    __shared__ float invq[QN];
    __shared__ float fq[QN];
    __shared__ float es[PP];
    int n = blockIdx.x, t = threadIdx.x;
    int lane = t & 31, w = t >> 5;
    const float NINF = __int_as_float(0xff800000u);

    if (t < PP) {
        sidx[t] = indices[n * PP + t];
        smk[t]  = mask[n * PP + t];
    }
    if (t < QN) tqs[t] = g_tq[t];
    __syncthreads();

    // Phase A: gather scores + pf
    {
        int p = t & 63, half = t >> 6;
        int idx = sidx[p];
        float4 v0, v1;
        if (smk[p] != 0u) {
            const float4* sp4 = reinterpret_cast<const float4*>(g_sp + (size_t)idx * QN + half * 8);
            v0 = sp4[0]; v1 = sp4[1];
        } else {
            v0 = make_float4(NINF, NINF, NINF, NINF);
            v1 = v0;
        }
        int q0 = half * 8;
        S[q0 + 0][p + 1] = v0.x; S[q0 + 1][p + 1] = v0.y;
        S[q0 + 2][p + 1] = v0.z; S[q0 + 3][p + 1] = v0.w;
        S[q0 + 4][p + 1] = v1.x; S[q0 + 5][p + 1] = v1.y;
        S[q0 + 6][p + 1] = v1.z; S[q0 + 7][p + 1] = v1.w;
        if (t < PP) pfs[t] = g_pf[sidx[t]];
    }
    if (t < QN) S[t][0] = g_sself[t];
    __syncthreads();

    // Phase B: per-q exp (unnormalized), inv-sum, and fused f[q] projection
    {
        float bf0 = bf[0];
#pragma unroll
        for (int qi = 0; qi < 4; qi++) {
            int q = w * 4 + qi;
            float v0 = S[q][lane], v1 = S[q][lane + 32];
            float v2 = (lane == 0) ? S[q][64] : NINF;
            float mx = fmaxf(fmaxf(v0, v1), v2);
#pragma unroll
            for (int o = 16; o; o >>= 1) mx = fmaxf(mx, __shfl_xor_sync(0xffffffffu, mx, o));
            float e0 = expf(v0 - mx), e1 = expf(v1 - mx);
            float e2 = (lane == 0) ? expf(v2 - mx) : 0.f;
            float s = e0 + e1 + e2;
#pragma unroll
            for (int o = 16; o; o >>= 1) s += __shfl_xor_sync(0xffffffffu, s, o);
            S[q][lane] = e0; S[q][lane + 32] = e1;
            if (lane == 0) S[q][64] = e2;
            // f[q] = (sum_slot e_slot * proj_slot)/s + bf  (slot0 -> tq[q], slot p+1 -> pf[idx_p])
            float pr0 = (lane == 0) ? tqs[q] : pfs[lane - 1];
            float fp = e0 * pr0 + e1 * pfs[lane + 31];
            if (lane == 0) fp += e2 * pfs[63];
#pragma unroll
            for (int o = 16; o; o >>= 1) fp += __shfl_xor_sync(0xffffffffu, fp, o);
            if (lane == 0) {
                invq[q] = 1.f / s;
                fq[q] = fp / s + bf0;
            }
        }
    }
    __syncthreads();

    // Phase C: fusion softmax over q (redundant per thread), c[q] = fw[q]*invq[q]
    float c[QN];
    {
        float fv[QN], mx = -3.4e38f;
#pragma unroll
        for (int q = 0; q < QN; q++) { fv[q] = fq[q]; mx = fmaxf(mx, fv[q]); }
        float s = 0.f;
#pragma unroll
        for (int q = 0; q < QN; q++) { fv[q] = expf(fv[q] - mx); s += fv[q]; }
        float inv = 1.f / s;
#pragma unroll
        for (int q = 0; q < QN; q++) c[q] = fv[q] * inv * invq[q];
    }

    // Phase D: effective per-row weights e[p]
    if (t < PP) {
        float ep = 0.f;
#pragma unroll
        for (int q = 0; q < QN; q++) ep += c[q] * S[q][t + 1];
        es[t] = ep;
    }
    __syncthreads();

    // Phase E: output accumulation (float4 over d)
    float4 o = make_float4(0.f, 0.f, 0.f, 0.f);
    {
        const float4* VQ4 = reinterpret_cast<const float4*>(g_VQ);
#pragma unroll
        for (int q = 0; q < QN; q++) {
            float c0 = c[q] * S[q][0];
            float4 vq = VQ4[q * 128 + t];
            o.x += c0 * vq.x; o.y += c0 * vq.y;
            o.z += c0 * vq.z; o.w += c0 * vq.w;
        }
    }
    const float4* Vp4 = reinterpret_cast<const float4*>(g_Vp);
#pragma unroll 8
    for (int p = 0; p < PP; p++) {
        float ep = es[p];
        if (ep != 0.f) {
            float4 v = Vp4[(size_t)sidx[p] * 128 + t];
            o.x += ep * v.x; o.y += ep * v.y;
            o.z += ep * v.z; o.w += ep * v.w;
        }
    }
    reinterpret_cast<float4*>(out)[(size_t)n * 128 + t] = o;
}

// ---------------------------------------------------------------------------
extern "C" void kernel_launch(void* const* d_in, const int* in_sizes, int n_in,
                              void* d_out, int out_size) {
    (void)in_sizes; (void)n_in; (void)out_size;
    const float* patch   = (const float*)d_in[0];
    const float* query   = (const float*)d_in[1];
    const float* Wk      = (const float*)d_in[2];
    const float* bk      = (const float*)d_in[3];
    const float* Wv      = (const float*)d_in[4];
    const float* bv      = (const float*)d_in[5];
    const float* Wf      = (const float*)d_in[6];
    const float* bf      = (const float*)d_in[7];
    const int* indices   = (const int*)d_in[8];
    const unsigned* mask = (const unsigned*)d_in[9];
    float* out           = (float*)d_out;

    k_pre<<<dim3(QN, 2), D>>>(query, Wk, Wv, bv);
    k_self<<<1, D>>>(query, bk, Wf);
    k_sp<<<NT / 16, D>>>(patch);
    k_gemm<<<dim3(D / BN, NT / BM), 64>>>(patch, Wv, bv);
    k_pf<<<NT / 8, 256>>>(Wf);
    k_combine<<<NG, 128>>>(indices, mask, bf, out);
}

// round 6
// speedup vs baseline: 1.3381x; 1.2748x over previous
#include <cuda_runtime.h>
#include <cuda_bf16.h>
#include <math.h>
#include <stdint.h>

// Problem constants
#define D   512
#define QN  16
#define NT  4096   // B*L tokens
#define NG  512    // N gathered groups
#define PP  64     // group size P

#define SCALE 0.04419417382415922f  // 1/sqrt(512)

// Scratch (allocation-free: __device__ globals)
__device__ float g_Vp[NT * D];            // patch @ Wv + bv      [4096,512]
__device__ float g_WvT[D * D];            // Wv^T (fp32)          [512,512]
__device__ __nv_bfloat16 g_Ahi[NT * D];   // bf16 hi split of patch
__device__ __nv_bfloat16 g_Alo[NT * D];   // bf16 lo split of patch
__device__ __nv_bfloat16 g_Bhi[D * D];    // bf16 hi split of Wv^T ([n][k])
__device__ __nv_bfloat16 g_Blo[D * D];    // bf16 lo split of Wv^T
__device__ float g_sp[NT * QN];           // scaled patch scores  [4096,16]
__device__ float g_VQ[QN * D];            // Q0 @ Wv + bv         [16,512]
__device__ float g_Ak[QN * D];            // (Wk @ Q0^T)^T        [16,512]
__device__ float g_pf[NT];                // Vp @ Wf              [4096]
__device__ float g_tq[QN];                // VQ @ Wf              [16]
__device__ float g_sself[QN];             // self-token scores    [16]
__device__ float g_qbk[QN];               // Q0[q] . bk           [16]

// ---- PTX helpers (all sm_80-level, valid for compute_103 target) -----------
__device__ __forceinline__ uint32_t smem_u32(const void* p) {
    uint32_t a;
    asm("{ .reg .u64 tmp; cvta.to.shared.u64 tmp, %1; cvt.u32.u64 %0, tmp; }"
        : "=r"(a) : "l"(p));
    return a;
}
__device__ __forceinline__ void cp16(uint32_t sdst, const void* gsrc) {
    asm volatile("cp.async.cg.shared.global [%0], [%1], 16;"
                 :: "r"(sdst), "l"(gsrc) : "memory");
}
#define CP_COMMIT() asm volatile("cp.async.commit_group;" ::: "memory")
#define CP_WAIT(n)  asm volatile("cp.async.wait_group %0;" :: "n"(n) : "memory")

__device__ __forceinline__ void ldm_x4(uint32_t* r, uint32_t addr) {
    asm volatile("ldmatrix.sync.aligned.m8n8.x4.shared.b16 {%0,%1,%2,%3}, [%4];"
                 : "=r"(r[0]), "=r"(r[1]), "=r"(r[2]), "=r"(r[3]) : "r"(addr));
}
__device__ __forceinline__ void mma16816(float* c, const uint32_t* a, const uint32_t* b) {
    asm volatile("mma.sync.aligned.m16n8k16.row.col.f32.bf16.bf16.f32 "
                 "{%0,%1,%2,%3}, {%4,%5,%6,%7}, {%8,%9}, {%0,%1,%2,%3};"
                 : "+f"(c[0]), "+f"(c[1]), "+f"(c[2]), "+f"(c[3])
                 : "r"(a[0]), "r"(a[1]), "r"(a[2]), "r"(a[3]), "r"(b[0]), "r"(b[1]));
}

// ---------------------------------------------------------------------------
// k_split_patch: bf16 hi/lo split of patch. grid 2048 x 256, float4 each.
// ---------------------------------------------------------------------------
__global__ __launch_bounds__(256) void k_split_patch(const float* __restrict__ patch) {
    int i = blockIdx.x * 256 + threadIdx.x;
    float4 v = reinterpret_cast<const float4*>(patch)[i];
    __nv_bfloat162 h0, h1, l0, l1;
    h0.x = __float2bfloat16_rn(v.x); l0.x = __float2bfloat16_rn(v.x - __bfloat162float(h0.x));
    h0.y = __float2bfloat16_rn(v.y); l0.y = __float2bfloat16_rn(v.y - __bfloat162float(h0.y));
    h1.x = __float2bfloat16_rn(v.z); l1.x = __float2bfloat16_rn(v.z - __bfloat162float(h1.x));
    h1.y = __float2bfloat16_rn(v.w); l1.y = __float2bfloat16_rn(v.w - __bfloat162float(h1.y));
    reinterpret_cast<__nv_bfloat162*>(g_Ahi)[2 * i]     = h0;
    reinterpret_cast<__nv_bfloat162*>(g_Ahi)[2 * i + 1] = h1;
    reinterpret_cast<__nv_bfloat162*>(g_Alo)[2 * i]     = l0;
    reinterpret_cast<__nv_bfloat162*>(g_Alo)[2 * i + 1] = l1;
}

// ---------------------------------------------------------------------------
// k_split_wv: transpose Wv -> WvT (fp32) + bf16 hi/lo splits. 64 blocks x 256.
// ---------------------------------------------------------------------------
__global__ __launch_bounds__(256) void k_split_wv(const float* __restrict__ Wv) {
    __shared__ float tile[64][65];
    int c0 = (blockIdx.x & 7) * 64, r0 = (blockIdx.x >> 3) * 64;
    int j = threadIdx.x & 63, i0 = threadIdx.x >> 6;
#pragma unroll
    for (int k = 0; k < 16; k++) {
        int i = i0 + k * 4;
        tile[i][j] = Wv[(size_t)(r0 + i) * D + c0 + j];
    }
    __syncthreads();
#pragma unroll
    for (int k = 0; k < 16; k++) {
        int i = i0 + k * 4;
        float v = tile[j][i];                 // Wv[r0+j][c0+i]
        size_t o = (size_t)(c0 + i) * D + r0 + j;
        g_WvT[o] = v;
        __nv_bfloat16 h = __float2bfloat16_rn(v);
        g_Bhi[o] = h;
        g_Blo[o] = __float2bfloat16_rn(v - __bfloat162float(h));
    }
}

// ---------------------------------------------------------------------------
// k_pre: grid (16, 2), block 512. Coalesced row-dots.
//  y==0: VQ[q][t] = bv[t] + q0 . WvT[t,:]
//  y==1: Ak[q][t] =         q0 . Wk[t,:]
// ---------------------------------------------------------------------------
__global__ void k_pre(const float* __restrict__ query, const float* __restrict__ Wk,
                      const float* __restrict__ bv) {
    __shared__ float q0[D];
    int q = blockIdx.x, t = threadIdx.x;
    q0[t] = query[q * D + t];
    __syncthreads();
    const float* base = blockIdx.y ? Wk : g_WvT;
    const float4* wr = reinterpret_cast<const float4*>(base + (size_t)t * D);
    float a0 = 0.f, a1 = 0.f;
#pragma unroll 8
    for (int i = 0; i < D / 8; i++) {
        float4 w0 = wr[2 * i], w1 = wr[2 * i + 1];
        a0 += w0.x * q0[8*i+0] + w0.y * q0[8*i+1] + w0.z * q0[8*i+2] + w0.w * q0[8*i+3];
        a1 += w1.x * q0[8*i+4] + w1.y * q0[8*i+5] + w1.z * q0[8*i+6] + w1.w * q0[8*i+7];
    }
    float r = a0 + a1;
    if (blockIdx.y) g_Ak[q * D + t] = r;
    else            g_VQ[q * D + t] = r + bv[t];
}

// ---------------------------------------------------------------------------
// k_self: 1 block, 512 threads. Warp q: s_self[q], qbk[q], tq[q] = VQ[q].Wf
// ---------------------------------------------------------------------------
__global__ void k_self(const float* __restrict__ query, const float* __restrict__ bk,
                       const float* __restrict__ Wf) {
    int q = threadIdx.x >> 5, lane = threadIdx.x & 31;
    float s = 0.f, sb = 0.f, tv = 0.f;
#pragma unroll
    for (int d = lane; d < D; d += 32) {
        float qv = query[q * D + d];
        s  += qv * g_Ak[q * D + d];
        sb += qv * bk[d];
        tv += g_VQ[q * D + d] * Wf[d];
    }
#pragma unroll
    for (int o = 16; o; o >>= 1) {
        s  += __shfl_xor_sync(0xffffffffu, s, o);
        sb += __shfl_xor_sync(0xffffffffu, sb, o);
        tv += __shfl_xor_sync(0xffffffffu, tv, o);
    }
    if (lane == 0) {
        g_qbk[q] = sb;
        g_sself[q] = (s + sb) * SCALE;
        g_tq[q] = tv;
    }
}

// ---------------------------------------------------------------------------
// k_sp: grid 256, block 512 (16 warps). sp[t][q] = (patch[t].Ak[q] + qbk[q])*scale
// ---------------------------------------------------------------------------
__global__ void k_sp(const float* __restrict__ patch) {
    __shared__ float Aks[QN * D];
    __shared__ float qb[QN];
    int t = threadIdx.x;
    float4* As4 = reinterpret_cast<float4*>(Aks);
    const float4* g4 = reinterpret_cast<const float4*>(g_Ak);
#pragma unroll
    for (int i = 0; i < 4; i++) As4[t + i * 512] = g4[t + i * 512];
    if (t < QN) qb[t] = g_qbk[t];
    __syncthreads();

    int w = t >> 5, lane = t & 31;
    int row = blockIdx.x * 16 + w;
    const float* pr = patch + (size_t)row * D;
    float acc[QN];
#pragma unroll
    for (int q = 0; q < QN; q++) acc[q] = 0.f;
#pragma unroll
    for (int c = 0; c < D / 32; c++) {
        float pv = pr[lane + c * 32];
#pragma unroll
        for (int q = 0; q < QN; q++) acc[q] += pv * Aks[q * D + lane + c * 32];
    }
#pragma unroll
    for (int q = 0; q < QN; q++) {
        float v = acc[q];
#pragma unroll
        for (int o = 16; o; o >>= 1) v += __shfl_xor_sync(0xffffffffu, v, o);
        if (lane == 0) g_sp[row * QN + q] = (v + qb[q]) * SCALE;
    }
}

// ---------------------------------------------------------------------------
// k_gemm_mma: Vp = patch @ Wv + bv via mma.sync bf16 (2-term split, 3 products)
// CTA tile 128x128, 256 threads (2x4 warps, warp tile 64x32), K-chunk 32,
// cp.async double-buffered. Smem rows pitch 80B (16B-aligned, ldmatrix
// conflict-free: 20-bank stride cycles all 8 phases).
// Grid (512/128, 4096/128) = (4, 32) = 128 CTAs.
// ---------------------------------------------------------------------------
#define MAT_B   10240          // 128 rows * 80 B
#define STAGE_B (4 * MAT_B)    // Ahi, Alo, Bhi, Blo
#define SMEM_MMA (2 * STAGE_B) // 81920

__global__ __launch_bounds__(256) void k_gemm_mma(const float* __restrict__ bv) {
    extern __shared__ char sm[];
    uint32_t sbase = smem_u32(sm);
    int t = threadIdx.x, wid = t >> 5, lane = t & 31;
    int m0 = blockIdx.y * 128, n0 = blockIdx.x * 128;
    int wm = wid >> 2, wn = wid & 3;

    float acc[4][4][4];
#pragma unroll
    for (int i = 0; i < 4; i++)
#pragma unroll
        for (int j = 0; j < 4; j++)
#pragma unroll
            for (int k = 0; k < 4; k++) acc[i][j][k] = 0.f;

    // cp.async task mapping: i-th op -> matrix i>>1, rem = (i&1)*256 + t
    const __nv_bfloat16* gb[4] = {g_Ahi, g_Alo, g_Bhi, g_Blo};
    int row4[4], seg4[4];   // per i-pair: r = rem>>2, seg = rem&3
#pragma unroll
    for (int h = 0; h < 2; h++) {
        int rem = h * 256 + t;
        row4[h] = rem >> 2; seg4[h] = rem & 3;
    }

    auto load_chunk = [&](int c) {
        int s = c & 1, k0 = c * 32;
        uint32_t base = sbase + s * STAGE_B;
#pragma unroll
        for (int i = 0; i < 8; i++) {
            int mat = i >> 1, h = i & 1;
            int r = row4[h], seg = seg4[h];
            const __nv_bfloat16* src = gb[mat] +
                (size_t)((mat < 2 ? m0 : n0) + r) * D + k0 + seg * 8;
            cp16(base + mat * MAT_B + r * 80 + seg * 16, src);
        }
        CP_COMMIT();
    };

    // ldmatrix lane offsets
    uint32_t aoff = (uint32_t)((wm * 64 + (lane & 15)) * 80 + (lane >> 4) * 16);
    uint32_t boff = (uint32_t)((wn * 32 + (lane & 7) + ((lane >> 4) & 1) * 8) * 80
                               + ((lane >> 3) & 1) * 16);

    load_chunk(0);
    for (int c = 0; c < 16; c++) {
        if (c < 15) { load_chunk(c + 1); CP_WAIT(1); }
        else        { CP_WAIT(0); }
        __syncthreads();
        uint32_t st = sbase + (c & 1) * STAGE_B;
#pragma unroll
        for (int ks = 0; ks < 2; ks++) {
            uint32_t ah[4][4], al[4][4], bh[2][4], bl[2][4];
#pragma unroll
            for (int mt = 0; mt < 4; mt++) {
                ldm_x4(ah[mt], st + aoff + mt * (16 * 80) + ks * 32);
                ldm_x4(al[mt], st + MAT_B + aoff + mt * (16 * 80) + ks * 32);
            }
#pragma unroll
            for (int np = 0; np < 2; np++) {
                ldm_x4(bh[np], st + 2 * MAT_B + boff + np * (16 * 80) + ks * 32);
                ldm_x4(bl[np], st + 3 * MAT_B + boff + np * (16 * 80) + ks * 32);
            }
#pragma unroll
            for (int mt = 0; mt < 4; mt++)
#pragma unroll
                for (int np = 0; np < 2; np++) {
                    mma16816(acc[mt][2 * np],     ah[mt], &bh[np][0]);
                    mma16816(acc[mt][2 * np + 1], ah[mt], &bh[np][2]);
                    mma16816(acc[mt][2 * np],     ah[mt], &bl[np][0]);
                    mma16816(acc[mt][2 * np + 1], ah[mt], &bl[np][2]);
                    mma16816(acc[mt][2 * np],     al[mt], &bh[np][0]);
                    mma16816(acc[mt][2 * np + 1], al[mt], &bh[np][2]);
                }
        }
        __syncthreads();
    }

    // Epilogue: direct reg -> gmem (float2 per fragment half), bias added
    int g = lane >> 2, tig = lane & 3;
#pragma unroll
    for (int mt = 0; mt < 4; mt++) {
        int r = m0 + wm * 64 + mt * 16 + g;
#pragma unroll
        for (int nt = 0; nt < 4; nt++) {
            int col = n0 + wn * 32 + nt * 8 + tig * 2;
            float b0 = __ldg(bv + col), b1 = __ldg(bv + col + 1);
            float2 v0 = make_float2(acc[mt][nt][0] + b0, acc[mt][nt][1] + b1);
            float2 v1 = make_float2(acc[mt][nt][2] + b0, acc[mt][nt][3] + b1);
            *reinterpret_cast<float2*>(&g_Vp[(size_t)r * D + col]) = v0;
            *reinterpret_cast<float2*>(&g_Vp[(size_t)(r + 8) * D + col]) = v1;
        }
    }
}

// ---------------------------------------------------------------------------
// k_pf: pf[t] = Vp[t] . Wf.  grid 512, block 256.
// ---------------------------------------------------------------------------
__global__ __launch_bounds__(256) void k_pf(const float* __restrict__ Wf) {
    int row = blockIdx.x * 8 + (threadIdx.x >> 5);
    int lane = threadIdx.x & 31;
    float s = 0.f;
#pragma unroll
    for (int i = 0; i < D / 32; i++)
        s += g_Vp[(size_t)row * D + lane + i * 32] * Wf[lane + i * 32];
#pragma unroll
    for (int o = 16; o; o >>= 1) s += __shfl_xor_sync(0xffffffffu, s, o);
    if (lane == 0) g_pf[row] = s;
}

// ---------------------------------------------------------------------------
// k_combine: one block per group n. Collapsed form:
//  out[d] = sum_q c0[q]*VQ[q,d] + sum_p e[p]*Vp[idx_p,d]
// ---------------------------------------------------------------------------
__global__ __launch_bounds__(128) void k_combine(const int* __restrict__ indices,
                                                 const unsigned* __restrict__ mask,
                                                 const float* __restrict__ bf,
                                                 float* __restrict__ out) {
    __shared__ float S[QN][72];
    __shared__ int sidx[PP];
    __shared__ unsigned smk[PP];
    __shared__ float pfs[PP];
    __shared__ float tqs[QN];
    __shared__ float invq[QN];
    __shared__ float fq[QN];
    __shared__ float es[PP];
    int n = blockIdx.x, t = threadIdx.x;
    int lane = t & 31, w = t >> 5;
    const float NINF = __int_as_float(0xff800000u);

    if (t < PP) {
        sidx[t] = indices[n * PP + t];
        smk[t]  = mask[n * PP + t];
    }
    if (t < QN) tqs[t] = g_tq[t];
    __syncthreads();

    {
        int p = t & 63, half = t >> 6;
        int idx = sidx[p];
        float4 v0, v1;
        if (smk[p] != 0u) {
            const float4* sp4 = reinterpret_cast<const float4*>(g_sp + (size_t)idx * QN + half * 8);
            v0 = sp4[0]; v1 = sp4[1];
        } else {
            v0 = make_float4(NINF, NINF, NINF, NINF);
            v1 = v0;
        }
        int q0 = half * 8;
        S[q0 + 0][p + 1] = v0.x; S[q0 + 1][p + 1] = v0.y;
        S[q0 + 2][p + 1] = v0.z; S[q0 + 3][p + 1] = v0.w;
        S[q0 + 4][p + 1] = v1.x; S[q0 + 5][p + 1] = v1.y;
        S[q0 + 6][p + 1] = v1.z; S[q0 + 7][p + 1] = v1.w;
        if (t < PP) pfs[t] = g_pf[sidx[t]];
    }
    if (t < QN) S[t][0] = g_sself[t];
    __syncthreads();

    {
        float bf0 = bf[0];
#pragma unroll
        for (int qi = 0; qi < 4; qi++) {
            int q = w * 4 + qi;
            float v0 = S[q][lane], v1 = S[q][lane + 32];
            float v2 = (lane == 0) ? S[q][64] : NINF;
            float mx = fmaxf(fmaxf(v0, v1), v2);
#pragma unroll
            for (int o = 16; o; o >>= 1) mx = fmaxf(mx, __shfl_xor_sync(0xffffffffu, mx, o));
            float e0 = expf(v0 - mx), e1 = expf(v1 - mx);
            float e2 = (lane == 0) ? expf(v2 - mx) : 0.f;
            float s = e0 + e1 + e2;
#pragma unroll
            for (int o = 16; o; o >>= 1) s += __shfl_xor_sync(0xffffffffu, s, o);
            S[q][lane] = e0; S[q][lane + 32] = e1;
            if (lane == 0) S[q][64] = e2;
            float pr0 = (lane == 0) ? tqs[q] : pfs[lane - 1];
            float fp = e0 * pr0 + e1 * pfs[lane + 31];
            if (lane == 0) fp += e2 * pfs[63];
#pragma unroll
            for (int o = 16; o; o >>= 1) fp += __shfl_xor_sync(0xffffffffu, fp, o);
            if (lane == 0) {
                invq[q] = 1.f / s;
                fq[q] = fp / s + bf0;
            }
        }
    }
    __syncthreads();

    float c[QN];
    {
        float fv[QN], mx = -3.4e38f;
#pragma unroll
        for (int q = 0; q < QN; q++) { fv[q] = fq[q]; mx = fmaxf(mx, fv[q]); }
        float s = 0.f;
#pragma unroll
        for (int q = 0; q < QN; q++) { fv[q] = expf(fv[q] - mx); s += fv[q]; }
        float inv = 1.f / s;
#pragma unroll
        for (int q = 0; q < QN; q++) c[q] = fv[q] * inv * invq[q];
    }

    if (t < PP) {
        float ep = 0.f;
#pragma unroll
        for (int q = 0; q < QN; q++) ep += c[q] * S[q][t + 1];
        es[t] = ep;
    }
    __syncthreads();

    float4 o = make_float4(0.f, 0.f, 0.f, 0.f);
    {
        const float4* VQ4 = reinterpret_cast<const float4*>(g_VQ);
#pragma unroll
        for (int q = 0; q < QN; q++) {
            float c0 = c[q] * S[q][0];
            float4 vq = VQ4[q * 128 + t];
            o.x += c0 * vq.x; o.y += c0 * vq.y;
            o.z += c0 * vq.z; o.w += c0 * vq.w;
        }
    }
    const float4* Vp4 = reinterpret_cast<const float4*>(g_Vp);
#pragma unroll 8
    for (int p = 0; p < PP; p++) {
        float ep = es[p];
        if (ep != 0.f) {
            float4 v = Vp4[(size_t)sidx[p] * 128 + t];
            o.x += ep * v.x; o.y += ep * v.y;
            o.z += ep * v.z; o.w += ep * v.w;
        }
    }
    reinterpret_cast<float4*>(out)[(size_t)n * 128 + t] = o;
}

// ---------------------------------------------------------------------------
extern "C" void kernel_launch(void* const* d_in, const int* in_sizes, int n_in,
                              void* d_out, int out_size) {
    (void)in_sizes; (void)n_in; (void)out_size;
    const float* patch   = (const float*)d_in[0];
    const float* query   = (const float*)d_in[1];
    const float* Wk      = (const float*)d_in[2];
    const float* bk      = (const float*)d_in[3];
    const float* Wv      = (const float*)d_in[4];
    const float* bv      = (const float*)d_in[5];
    const float* Wf      = (const float*)d_in[6];
    const float* bf      = (const float*)d_in[7];
    const int* indices   = (const int*)d_in[8];
    const unsigned* mask = (const unsigned*)d_in[9];
    float* out           = (float*)d_out;

    cudaFuncSetAttribute(k_gemm_mma, cudaFuncAttributeMaxDynamicSharedMemorySize, SMEM_MMA);

    k_split_patch<<<NT * D / 4 / 256, 256>>>(patch);
    k_split_wv<<<64, 256>>>(Wv);
    k_pre<<<dim3(QN, 2), D>>>(query, Wk, bv);
    k_self<<<1, D>>>(query, bk, Wf);
    k_sp<<<NT / 16, D>>>(patch);
    k_gemm_mma<<<dim3(4, 32), 256, SMEM_MMA>>>(bv);
    k_pf<<<NT / 8, 256>>>(Wf);
    k_combine<<<NG, 128>>>(indices, mask, bf, out);
}

// round 8
// speedup vs baseline: 1.4517x; 1.0849x over previous
#include <cuda_runtime.h>
#include <cuda_bf16.h>
#include <math.h>
#include <stdint.h>

// Problem constants
#define D   512
#define QN  16
#define NT  4096   // B*L tokens
#define NG  512    // N gathered groups
#define PP  64     // group size P

#define SCALE 0.04419417382415922f  // 1/sqrt(512)

// Scratch (allocation-free: __device__ globals)
__device__ float g_Vp[NT * D];            // patch @ Wv + bv      [4096,512]
__device__ __nv_bfloat16 g_Ahi[NT * D];   // bf16 hi split of patch
__device__ __nv_bfloat16 g_Alo[NT * D];   // bf16 lo split of patch
__device__ __nv_bfloat16 g_Bhi[D * D];    // bf16 hi split of Wv^T ([n][k])
__device__ __nv_bfloat16 g_Blo[D * D];    // bf16 lo split of Wv^T
__device__ float g_sp[NT * QN];           // scaled patch scores  [4096,16]
__device__ float g_VQ[QN * D];            // Q0 @ Wv + bv         [16,512]
__device__ float g_Ak[QN * D];            // (Wk @ Q0^T)^T        [16,512]
__device__ float g_pfp[4][NT];            // partial Vp @ Wf per n-tile
__device__ float g_tq[QN];                // VQ @ Wf              [16]
__device__ float g_sself[QN];             // self-token scores    [16]
__device__ float g_qbk[QN];               // Q0[q] . bk           [16]

// ---- PTX helpers (all sm_80-level, valid for compute_103 target) -----------
__device__ __forceinline__ uint32_t smem_u32(const void* p) {
    uint32_t a;
    asm("{ .reg .u64 tmp; cvta.to.shared.u64 tmp, %1; cvt.u32.u64 %0, tmp; }"
        : "=r"(a) : "l"(p));
    return a;
}
__device__ __forceinline__ void cp16(uint32_t sdst, const void* gsrc) {
    asm volatile("cp.async.cg.shared.global [%0], [%1], 16;"
                 :: "r"(sdst), "l"(gsrc) : "memory");
}
#define CP_COMMIT() asm volatile("cp.async.commit_group;" ::: "memory")
#define CP_WAIT(n)  asm volatile("cp.async.wait_group %0;" :: "n"(n) : "memory")

__device__ __forceinline__ void ldm_x4(uint32_t* r, uint32_t addr) {
    asm volatile("ldmatrix.sync.aligned.m8n8.x4.shared.b16 {%0,%1,%2,%3}, [%4];"
                 : "=r"(r[0]), "=r"(r[1]), "=r"(r[2]), "=r"(r[3]) : "r"(addr));
}
__device__ __forceinline__ void mma16816(float* c, const uint32_t* a, const uint32_t* b) {
    asm volatile("mma.sync.aligned.m16n8k16.row.col.f32.bf16.bf16.f32 "
                 "{%0,%1,%2,%3}, {%4,%5,%6,%7}, {%8,%9}, {%0,%1,%2,%3};"
                 : "+f"(c[0]), "+f"(c[1]), "+f"(c[2]), "+f"(c[3])
                 : "r"(a[0]), "r"(a[1]), "r"(a[2]), "r"(a[3]), "r"(b[0]), "r"(b[1]));
}

// ---------------------------------------------------------------------------
// k_split: merged prep. Blocks 0..2047: bf16 hi/lo split of patch (float4 per
// thread). Blocks 2048..2111: Wv transpose + bf16 hi/lo splits.
// ---------------------------------------------------------------------------
__global__ __launch_bounds__(256) void k_split(const float* __restrict__ patch,
                                               const float* __restrict__ Wv) {
    if (blockIdx.x < 2048) {
        int i = blockIdx.x * 256 + threadIdx.x;
        float4 v = reinterpret_cast<const float4*>(patch)[i];
        __nv_bfloat162 h0, h1, l0, l1;
        h0.x = __float2bfloat16_rn(v.x); l0.x = __float2bfloat16_rn(v.x - __bfloat162float(h0.x));
        h0.y = __float2bfloat16_rn(v.y); l0.y = __float2bfloat16_rn(v.y - __bfloat162float(h0.y));
        h1.x = __float2bfloat16_rn(v.z); l1.x = __float2bfloat16_rn(v.z - __bfloat162float(h1.x));
        h1.y = __float2bfloat16_rn(v.w); l1.y = __float2bfloat16_rn(v.w - __bfloat162float(h1.y));
        reinterpret_cast<__nv_bfloat162*>(g_Ahi)[2 * i]     = h0;
        reinterpret_cast<__nv_bfloat162*>(g_Ahi)[2 * i + 1] = h1;
        reinterpret_cast<__nv_bfloat162*>(g_Alo)[2 * i]     = l0;
        reinterpret_cast<__nv_bfloat162*>(g_Alo)[2 * i + 1] = l1;
    } else {
        __shared__ float tile[64][65];
        int b = blockIdx.x - 2048;
        int c0 = (b & 7) * 64, r0 = (b >> 3) * 64;
        int j = threadIdx.x & 63, i0 = threadIdx.x >> 6;
#pragma unroll
        for (int k = 0; k < 16; k++) {
            int i = i0 + k * 4;
            tile[i][j] = Wv[(size_t)(r0 + i) * D + c0 + j];
        }
        __syncthreads();
#pragma unroll
        for (int k = 0; k < 16; k++) {
            int i = i0 + k * 4;
            float v = tile[j][i];                 // Wv[r0+j][c0+i]
            size_t o = (size_t)(c0 + i) * D + r0 + j;
            __nv_bfloat16 h = __float2bfloat16_rn(v);
            g_Bhi[o] = h;
            g_Blo[o] = __float2bfloat16_rn(v - __bfloat162float(h));
        }
    }
}

// ---------------------------------------------------------------------------
// k_pre: grid (16, 2), block 512. Fused projections + scalar reductions.
//  y==0: VQ[q][t] = bv[t] + sum_d q0[d]*Wv[d][t]   (coalesced over t)
//        + block-reduce tq[q] = VQ[q] . Wf
//  y==1: Ak[q][t] = q0 . Wk[t,:]
//        + block-reduce qbk[q] = q0.bk, sself[q] = (q0.Ak[q]+qbk)*scale
// ---------------------------------------------------------------------------
__global__ void k_pre(const float* __restrict__ query, const float* __restrict__ Wk,
                      const float* __restrict__ Wv, const float* __restrict__ bv,
                      const float* __restrict__ bk, const float* __restrict__ Wf) {
    __shared__ float q0[D];
    __shared__ float red[2][16];
    int q = blockIdx.x, t = threadIdx.x;
    int w = t >> 5, lane = t & 31;
    q0[t] = query[q * D + t];
    __syncthreads();

    float r0v = 0.f, r1v = 0.f;   // two reduction payloads
    if (blockIdx.y == 0) {
        float a0 = bv[t], a1 = 0.f;
#pragma unroll 8
        for (int d = 0; d < D; d += 2) {
            a0 += q0[d]     * Wv[d * D + t];
            a1 += q0[d + 1] * Wv[(d + 1) * D + t];
        }
        float r = a0 + a1;
        g_VQ[q * D + t] = r;
        r0v = r * Wf[t];          // -> tq[q]
    } else {
        const float4* wr = reinterpret_cast<const float4*>(Wk + (size_t)t * D);
        float a0 = 0.f, a1 = 0.f;
#pragma unroll 8
        for (int i = 0; i < D / 8; i++) {
            float4 w0 = wr[2 * i], w1 = wr[2 * i + 1];
            a0 += w0.x * q0[8*i+0] + w0.y * q0[8*i+1] + w0.z * q0[8*i+2] + w0.w * q0[8*i+3];
            a1 += w1.x * q0[8*i+4] + w1.y * q0[8*i+5] + w1.z * q0[8*i+6] + w1.w * q0[8*i+7];
        }
        float r = a0 + a1;
        g_Ak[q * D + t] = r;
        r0v = q0[t] * r;          // -> sself numerator
        r1v = q0[t] * bk[t];      // -> qbk
    }
#pragma unroll
    for (int o = 16; o; o >>= 1) {
        r0v += __shfl_xor_sync(0xffffffffu, r0v, o);
        r1v += __shfl_xor_sync(0xffffffffu, r1v, o);
    }
    if (lane == 0) { red[0][w] = r0v; red[1][w] = r1v; }
    __syncthreads();
    if (w == 0) {
        float x0 = (lane < 16) ? red[0][lane] : 0.f;
        float x1 = (lane < 16) ? red[1][lane] : 0.f;
#pragma unroll
        for (int o = 8; o; o >>= 1) {
            x0 += __shfl_xor_sync(0xffffffffu, x0, o);
            x1 += __shfl_xor_sync(0xffffffffu, x1, o);
        }
        if (lane == 0) {
            if (blockIdx.y == 0) {
                g_tq[q] = x0;
            } else {
                g_qbk[q] = x1;
                g_sself[q] = (x0 + x1) * SCALE;
            }
        }
    }
}

// ---------------------------------------------------------------------------
// k_sp: grid 256, block 512 (16 warps). sp[t][q] = (patch[t].Ak[q] + qbk[q])*scale
// ---------------------------------------------------------------------------
__global__ void k_sp(const float* __restrict__ patch) {
    __shared__ float Aks[QN * D];
    __shared__ float qb[QN];
    int t = threadIdx.x;
    float4* As4 = reinterpret_cast<float4*>(Aks);
    const float4* g4 = reinterpret_cast<const float4*>(g_Ak);
#pragma unroll
    for (int i = 0; i < 4; i++) As4[t + i * 512] = g4[t + i * 512];
    if (t < QN) qb[t] = g_qbk[t];
    __syncthreads();

    int w = t >> 5, lane = t & 31;
    int row = blockIdx.x * 16 + w;
    const float* pr = patch + (size_t)row * D;
    float acc[QN];
#pragma unroll
    for (int q = 0; q < QN; q++) acc[q] = 0.f;
#pragma unroll
    for (int c = 0; c < D / 32; c++) {
        float pv = pr[lane + c * 32];
#pragma unroll
        for (int q = 0; q < QN; q++) acc[q] += pv * Aks[q * D + lane + c * 32];
    }
#pragma unroll
    for (int q = 0; q < QN; q++) {
        float v = acc[q];
#pragma unroll
        for (int o = 16; o; o >>= 1) v += __shfl_xor_sync(0xffffffffu, v, o);
        if (lane == 0) g_sp[row * QN + q] = (v + qb[q]) * SCALE;
    }
}

// ---------------------------------------------------------------------------
// k_gemm_mma: Vp = patch @ Wv + bv via mma.sync bf16 (2-term split, 3 products)
// CTA tile 128x128, 256 threads (2x4 warps, warp tile 64x32), K-chunk 32,
// cp.async double-buffered, 80B smem row pitch (conflict-free ldmatrix).
// Epilogue additionally produces pf partials: g_pfp[bx][row] = tile_row . Wf.
// ---------------------------------------------------------------------------
#define MAT_B   10240          // 128 rows * 80 B
#define STAGE_B (4 * MAT_B)    // Ahi, Alo, Bhi, Blo
#define SMEM_MMA (2 * STAGE_B) // 81920

__global__ __launch_bounds__(256) void k_gemm_mma(const float* __restrict__ bv,
                                                  const float* __restrict__ Wf) {
    extern __shared__ char sm[];
    uint32_t sbase = smem_u32(sm);
    int t = threadIdx.x, wid = t >> 5, lane = t & 31;
    int m0 = blockIdx.y * 128, n0 = blockIdx.x * 128;
    int wm = wid >> 2, wn = wid & 3;

    float acc[4][4][4];
#pragma unroll
    for (int i = 0; i < 4; i++)
#pragma unroll
        for (int j = 0; j < 4; j++)
#pragma unroll
            for (int k = 0; k < 4; k++) acc[i][j][k] = 0.f;

    const __nv_bfloat16* gb[4] = {g_Ahi, g_Alo, g_Bhi, g_Blo};
    int row4[2], seg4[2];
#pragma unroll
    for (int h = 0; h < 2; h++) {
        int rem = h * 256 + t;
        row4[h] = rem >> 2; seg4[h] = rem & 3;
    }

    auto load_chunk = [&](int c) {
        int s = c & 1, k0 = c * 32;
        uint32_t base = sbase + s * STAGE_B;
#pragma unroll
        for (int i = 0; i < 8; i++) {
            int mat = i >> 1, h = i & 1;
            int r = row4[h], seg = seg4[h];
            const __nv_bfloat16* src = gb[mat] +
                (size_t)((mat < 2 ? m0 : n0) + r) * D + k0 + seg * 8;
            cp16(base + mat * MAT_B + r * 80 + seg * 16, src);
        }
        CP_COMMIT();
    };

    uint32_t aoff = (uint32_t)((wm * 64 + (lane & 15)) * 80 + (lane >> 4) * 16);
    uint32_t boff = (uint32_t)((wn * 32 + (lane & 7) + ((lane >> 4) & 1) * 8) * 80
                               + ((lane >> 3) & 1) * 16);

    load_chunk(0);
    for (int c = 0; c < 16; c++) {
        if (c < 15) { load_chunk(c + 1); CP_WAIT(1); }
        else        { CP_WAIT(0); }
        __syncthreads();
        uint32_t st = sbase + (c & 1) * STAGE_B;
#pragma unroll
        for (int ks = 0; ks < 2; ks++) {
            uint32_t ah[4][4], al[4][4], bh[2][4], bl[2][4];
#pragma unroll
            for (int mt = 0; mt < 4; mt++) {
                ldm_x4(ah[mt], st + aoff + mt * (16 * 80) + ks * 32);
                ldm_x4(al[mt], st + MAT_B + aoff + mt * (16 * 80) + ks * 32);
            }
#pragma unroll
            for (int np = 0; np < 2; np++) {
                ldm_x4(bh[np], st + 2 * MAT_B + boff + np * (16 * 80) + ks * 32);
                ldm_x4(bl[np], st + 3 * MAT_B + boff + np * (16 * 80) + ks * 32);
            }
#pragma unroll
            for (int mt = 0; mt < 4; mt++)
#pragma unroll
                for (int np = 0; np < 2; np++) {
                    mma16816(acc[mt][2 * np],     ah[mt], &bh[np][0]);
                    mma16816(acc[mt][2 * np + 1], ah[mt], &bh[np][2]);
                    mma16816(acc[mt][2 * np],     ah[mt], &bl[np][0]);
                    mma16816(acc[mt][2 * np + 1], ah[mt], &bl[np][2]);
                    mma16816(acc[mt][2 * np],     al[mt], &bh[np][0]);
                    mma16816(acc[mt][2 * np + 1], al[mt], &bh[np][2]);
                }
        }
        __syncthreads();
    }

    // Epilogue: bias add, store Vp, and pf partials (row . Wf over this tile)
    int g = lane >> 2, tig = lane & 3;
    float bcol0[4], bcol1[4], wcol0[4], wcol1[4];
#pragma unroll
    for (int nt = 0; nt < 4; nt++) {
        int col = n0 + wn * 32 + nt * 8 + tig * 2;
        bcol0[nt] = __ldg(bv + col); bcol1[nt] = __ldg(bv + col + 1);
        wcol0[nt] = __ldg(Wf + col); wcol1[nt] = __ldg(Wf + col + 1);
    }
    float* spf = reinterpret_cast<float*>(sm);  // [4][128], stages dead now
#pragma unroll
    for (int mt = 0; mt < 4; mt++) {
        int r = m0 + wm * 64 + mt * 16 + g;
        float pf0 = 0.f, pf1 = 0.f;
#pragma unroll
        for (int nt = 0; nt < 4; nt++) {
            int col = n0 + wn * 32 + nt * 8 + tig * 2;
            float2 v0 = make_float2(acc[mt][nt][0] + bcol0[nt], acc[mt][nt][1] + bcol1[nt]);
            float2 v1 = make_float2(acc[mt][nt][2] + bcol0[nt], acc[mt][nt][3] + bcol1[nt]);
            *reinterpret_cast<float2*>(&g_Vp[(size_t)r * D + col]) = v0;
            *reinterpret_cast<float2*>(&g_Vp[(size_t)(r + 8) * D + col]) = v1;
            pf0 += v0.x * wcol0[nt] + v0.y * wcol1[nt];
            pf1 += v1.x * wcol0[nt] + v1.y * wcol1[nt];
        }
        pf0 += __shfl_xor_sync(0xffffffffu, pf0, 1);
        pf0 += __shfl_xor_sync(0xffffffffu, pf0, 2);
        pf1 += __shfl_xor_sync(0xffffffffu, pf1, 1);
        pf1 += __shfl_xor_sync(0xffffffffu, pf1, 2);
        if (tig == 0) {
            int lr = wm * 64 + mt * 16 + g;
            spf[wn * 128 + lr] = pf0;
            spf[wn * 128 + lr + 8] = pf1;
        }
    }
    __syncthreads();
    if (t < 128) {
        g_pfp[blockIdx.x][m0 + t] =
            spf[t] + spf[128 + t] + spf[256 + t] + spf[384 + t];
    }
}

// ---------------------------------------------------------------------------
// k_combine: one block per group n. Collapsed form:
//  out[d] = sum_q c0[q]*VQ[q,d] + sum_p e[p]*Vp[idx_p,d]
// ---------------------------------------------------------------------------
__global__ __launch_bounds__(128) void k_combine(const int* __restrict__ indices,
                                                 const unsigned* __restrict__ mask,
                                                 const float* __restrict__ bf,
                                                 float* __restrict__ out) {
    __shared__ float S[QN][72];
    __shared__ int sidx[PP];
    __shared__ unsigned smk[PP];
    __shared__ float pfs[PP];
    __shared__ float tqs[QN];
    __shared__ float invq[QN];
    __shared__ float fq[QN];
    __shared__ float es[PP];
    int n = blockIdx.x, t = threadIdx.x;
    int lane = t & 31, w = t >> 5;
    const float NINF = __int_as_float(0xff800000u);

    if (t < PP) {
        sidx[t] = indices[n * PP + t];
        smk[t]  = mask[n * PP + t];
    }
    if (t < QN) tqs[t] = g_tq[t];
    __syncthreads();

    {
        int p = t & 63, half = t >> 6;
        int idx = sidx[p];
        float4 v0, v1;
        if (smk[p] != 0u) {
            const float4* sp4 = reinterpret_cast<const float4*>(g_sp + (size_t)idx * QN + half * 8);
            v0 = sp4[0]; v1 = sp4[1];
        } else {
            v0 = make_float4(NINF, NINF, NINF, NINF);
            v1 = v0;
        }
        int q0 = half * 8;
        S[q0 + 0][p + 1] = v0.x; S[q0 + 1][p + 1] = v0.y;
        S[q0 + 2][p + 1] = v0.z; S[q0 + 3][p + 1] = v0.w;
        S[q0 + 4][p + 1] = v1.x; S[q0 + 5][p + 1] = v1.y;
        S[q0 + 6][p + 1] = v1.z; S[q0 + 7][p + 1] = v1.w;
        if (t < PP) {
            int idx2 = sidx[t];
            pfs[t] = g_pfp[0][idx2] + g_pfp[1][idx2] + g_pfp[2][idx2] + g_pfp[3][idx2];
        }
    }
    if (t < QN) S[t][0] = g_sself[t];
    __syncthreads();

    {
        float bf0 = bf[0];
#pragma unroll
        for (int qi = 0; qi < 4; qi++) {
            int q = w * 4 + qi;
            float v0 = S[q][lane], v1 = S[q][lane + 32];
            float v2 = (lane == 0) ? S[q][64] : NINF;
            float mx = fmaxf(fmaxf(v0, v1), v2);
#pragma unroll
            for (int o = 16; o; o >>= 1) mx = fmaxf(mx, __shfl_xor_sync(0xffffffffu, mx, o));
            float e0 = expf(v0 - mx), e1 = expf(v1 - mx);
            float e2 = (lane == 0) ? expf(v2 - mx) : 0.f;
            float s = e0 + e1 + e2;
#pragma unroll
            for (int o = 16; o; o >>= 1) s += __shfl_xor_sync(0xffffffffu, s, o);
            S[q][lane] = e0; S[q][lane + 32] = e1;
            if (lane == 0) S[q][64] = e2;
            float pr0 = (lane == 0) ? tqs[q] : pfs[lane - 1];
            float fp = e0 * pr0 + e1 * pfs[lane + 31];
            if (lane == 0) fp += e2 * pfs[63];
#pragma unroll
            for (int o = 16; o; o >>= 1) fp += __shfl_xor_sync(0xffffffffu, fp, o);
            if (lane == 0) {
                invq[q] = 1.f / s;
                fq[q] = fp / s + bf0;
            }
        }
    }
    __syncthreads();

    float c[QN];
    {
        float fv[QN], mx = -3.4e38f;
#pragma unroll
        for (int q = 0; q < QN; q++) { fv[q] = fq[q]; mx = fmaxf(mx, fv[q]); }
        float s = 0.f;
#pragma unroll
        for (int q = 0; q < QN; q++) { fv[q] = expf(fv[q] - mx); s += fv[q]; }
        float inv = 1.f / s;
#pragma unroll
        for (int q = 0; q < QN; q++) c[q] = fv[q] * inv * invq[q];
    }

    if (t < PP) {
        float ep = 0.f;
#pragma unroll
        for (int q = 0; q < QN; q++) ep += c[q] * S[q][t + 1];
        es[t] = ep;
    }
    __syncthreads();

    float4 o = make_float4(0.f, 0.f, 0.f, 0.f);
    {
        const float4* VQ4 = reinterpret_cast<const float4*>(g_VQ);
#pragma unroll
        for (int q = 0; q < QN; q++) {
            float c0 = c[q] * S[q][0];
            float4 vq = VQ4[q * 128 + t];
            o.x += c0 * vq.x; o.y += c0 * vq.y;
            o.z += c0 * vq.z; o.w += c0 * vq.w;
        }
    }
    const float4* Vp4 = reinterpret_cast<const float4*>(g_Vp);
#pragma unroll 8
    for (int p = 0; p < PP; p++) {
        float ep = es[p];
        if (ep != 0.f) {
            float4 v = Vp4[(size_t)sidx[p] * 128 + t];
            o.x += ep * v.x; o.y += ep * v.y;
            o.z += ep * v.z; o.w += ep * v.w;
        }
    }
    reinterpret_cast<float4*>(out)[(size_t)n * 128 + t] = o;
}

// ---------------------------------------------------------------------------
extern "C" void kernel_launch(void* const* d_in, const int* in_sizes, int n_in,
                              void* d_out, int out_size) {
    (void)in_sizes; (void)n_in; (void)out_size;
    const float* patch   = (const float*)d_in[0];
    const float* query   = (const float*)d_in[1];
    const float* Wk      = (const float*)d_in[2];
    const float* bk      = (const float*)d_in[3];
    const float* Wv      = (const float*)d_in[4];
    const float* bv      = (const float*)d_in[5];
    const float* Wf      = (const float*)d_in[6];
    const float* bf      = (const float*)d_in[7];
    const int* indices   = (const int*)d_in[8];
    const unsigned* mask = (const unsigned*)d_in[9];
    float* out           = (float*)d_out;

    cudaFuncSetAttribute(k_gemm_mma, cudaFuncAttributeMaxDynamicSharedMemorySize, SMEM_MMA);

    k_split<<<2048 + 64, 256>>>(patch, Wv);
    k_pre<<<dim3(QN, 2), D>>>(query, Wk, Wv, bv, bk, Wf);
    k_sp<<<NT / 16, D>>>(patch);
    k_gemm_mma<<<dim3(4, 32), 256, SMEM_MMA>>>(bv, Wf);
    k_combine<<<NG, 128>>>(indices, mask, bf, out);
}

// round 10
// speedup vs baseline: 1.4906x; 1.0268x over previous
#include <cuda_runtime.h>
#include <cuda_bf16.h>
#include <math.h>
#include <stdint.h>

// Problem constants
#define D   512
#define QN  16
#define NT  4096   // B*L tokens
#define NG  512    // N gathered groups
#define PP  64     // group size P

#define SCALE 0.04419417382415922f  // 1/sqrt(512)

// Scratch (allocation-free: __device__ globals)
__device__ float g_Vp[NT * D];            // patch @ Wv + bv      [4096,512]
__device__ __nv_bfloat16 g_Ahi[NT * D];   // bf16 hi split of patch
__device__ __nv_bfloat16 g_Alo[NT * D];   // bf16 lo split of patch
__device__ __nv_bfloat16 g_Bhi[D * D];    // bf16 hi split of Wv^T ([n][k])
__device__ __nv_bfloat16 g_Blo[D * D];    // bf16 lo split of Wv^T
__device__ float g_sp[NT * QN];           // scaled patch scores  [4096,16]
__device__ float g_VQ[QN * D];            // Q0 @ Wv + bv         [16,512]
__device__ float g_Ak[QN * D];            // (Wk @ Q0^T)^T        [16,512]
__device__ float g_pfp[8][NT];            // partial Vp @ Wf per n-tile
__device__ float g_tq[QN];                // VQ @ Wf              [16]
__device__ float g_sself[QN];             // self-token scores    [16]
__device__ float g_qbk[QN];               // Q0[q] . bk           [16]

// ---- PTX helpers (all sm_80-level, valid for compute_103 target) -----------
__device__ __forceinline__ uint32_t smem_u32(const void* p) {
    uint32_t a;
    asm("{ .reg .u64 tmp; cvta.to.shared.u64 tmp, %1; cvt.u32.u64 %0, tmp; }"
        : "=r"(a) : "l"(p));
    return a;
}
__device__ __forceinline__ void cp16(uint32_t sdst, const void* gsrc) {
    asm volatile("cp.async.cg.shared.global [%0], [%1], 16;"
                 :: "r"(sdst), "l"(gsrc) : "memory");
}
#define CP_COMMIT() asm volatile("cp.async.commit_group;" ::: "memory")
#define CP_WAIT(n)  asm volatile("cp.async.wait_group %0;" :: "n"(n) : "memory")

__device__ __forceinline__ void ldm_x4(uint32_t* r, uint32_t addr) {
    asm volatile("ldmatrix.sync.aligned.m8n8.x4.shared.b16 {%0,%1,%2,%3}, [%4];"
                 : "=r"(r[0]), "=r"(r[1]), "=r"(r[2]), "=r"(r[3]) : "r"(addr));
}
__device__ __forceinline__ void mma16816(float* c, const uint32_t* a, const uint32_t* b) {
    asm volatile("mma.sync.aligned.m16n8k16.row.col.f32.bf16.bf16.f32 "
                 "{%0,%1,%2,%3}, {%4,%5,%6,%7}, {%8,%9}, {%0,%1,%2,%3};"
                 : "+f"(c[0]), "+f"(c[1]), "+f"(c[2]), "+f"(c[3])
                 : "r"(a[0]), "r"(a[1]), "r"(a[2]), "r"(a[3]), "r"(b[0]), "r"(b[1]));
}

// ---------------------------------------------------------------------------
// k_pre: grid (16, 2), block 512. Fused projections + scalar reductions.
// ---------------------------------------------------------------------------
__global__ void k_pre(const float* __restrict__ query, const float* __restrict__ Wk,
                      const float* __restrict__ Wv, const float* __restrict__ bv,
                      const float* __restrict__ bk, const float* __restrict__ Wf) {
    __shared__ float q0[D];
    __shared__ float red[2][16];
    int q = blockIdx.x, t = threadIdx.x;
    int w = t >> 5, lane = t & 31;
    q0[t] = query[q * D + t];
    __syncthreads();

    float r0v = 0.f, r1v = 0.f;
    if (blockIdx.y == 0) {
        float a0 = bv[t], a1 = 0.f;
#pragma unroll 8
        for (int d = 0; d < D; d += 2) {
            a0 += q0[d]     * Wv[d * D + t];
            a1 += q0[d + 1] * Wv[(d + 1) * D + t];
        }
        float r = a0 + a1;
        g_VQ[q * D + t] = r;
        r0v = r * Wf[t];
    } else {
        const float4* wr = reinterpret_cast<const float4*>(Wk + (size_t)t * D);
        float a0 = 0.f, a1 = 0.f;
#pragma unroll 8
        for (int i = 0; i < D / 8; i++) {
            float4 w0 = wr[2 * i], w1 = wr[2 * i + 1];
            a0 += w0.x * q0[8*i+0] + w0.y * q0[8*i+1] + w0.z * q0[8*i+2] + w0.w * q0[8*i+3];
            a1 += w1.x * q0[8*i+4] + w1.y * q0[8*i+5] + w1.z * q0[8*i+6] + w1.w * q0[8*i+7];
        }
        float r = a0 + a1;
        g_Ak[q * D + t] = r;
        r0v = q0[t] * r;
        r1v = q0[t] * bk[t];
    }
#pragma unroll
    for (int o = 16; o; o >>= 1) {
        r0v += __shfl_xor_sync(0xffffffffu, r0v, o);
        r1v += __shfl_xor_sync(0xffffffffu, r1v, o);
    }
    if (lane == 0) { red[0][w] = r0v; red[1][w] = r1v; }
    __syncthreads();
    if (w == 0) {
        float x0 = (lane < 16) ? red[0][lane] : 0.f;
        float x1 = (lane < 16) ? red[1][lane] : 0.f;
#pragma unroll
        for (int o = 8; o; o >>= 1) {
            x0 += __shfl_xor_sync(0xffffffffu, x0, o);
            x1 += __shfl_xor_sync(0xffffffffu, x1, o);
        }
        if (lane == 0) {
            if (blockIdx.y == 0) {
                g_tq[q] = x0;
            } else {
                g_qbk[q] = x1;
                g_sself[q] = (x0 + x1) * SCALE;
            }
        }
    }
}

// ---------------------------------------------------------------------------
// k_sp: fused. Blocks 0..255 (512 thr): sp scores for 16 token rows AND the
// bf16 hi/lo split of those patch rows (values already in registers).
// Blocks 256..319: Wv transpose + bf16 hi/lo split.
// ---------------------------------------------------------------------------
__global__ __launch_bounds__(512) void k_sp(const float* __restrict__ patch,
                                            const float* __restrict__ Wv) {
    __shared__ float Aks[QN * D];
    __shared__ float qb[QN];
    __shared__ float tile[64][65];
    int t = threadIdx.x;
    if (blockIdx.x < 256) {
        float4* As4 = reinterpret_cast<float4*>(Aks);
        const float4* g4 = reinterpret_cast<const float4*>(g_Ak);
#pragma unroll
        for (int i = 0; i < 4; i++) As4[t + i * 512] = g4[t + i * 512];
        if (t < QN) qb[t] = g_qbk[t];
        __syncthreads();

        int w = t >> 5, lane = t & 31;
        int row = blockIdx.x * 16 + w;
        const float* pr = patch + (size_t)row * D;
        float acc[QN];
#pragma unroll
        for (int q = 0; q < QN; q++) acc[q] = 0.f;
#pragma unroll
        for (int c = 0; c < D / 32; c++) {
            int col = lane + c * 32;
            float pv = pr[col];
            // bf16 hi/lo split ride-along
            __nv_bfloat16 h = __float2bfloat16_rn(pv);
            g_Ahi[(size_t)row * D + col] = h;
            g_Alo[(size_t)row * D + col] = __float2bfloat16_rn(pv - __bfloat162float(h));
#pragma unroll
            for (int q = 0; q < QN; q++) acc[q] += pv * Aks[q * D + col];
        }
#pragma unroll
        for (int q = 0; q < QN; q++) {
            float v = acc[q];
#pragma unroll
            for (int o = 16; o; o >>= 1) v += __shfl_xor_sync(0xffffffffu, v, o);
            if (lane == 0) g_sp[row * QN + q] = (v + qb[q]) * SCALE;
        }
    } else {
        int b = blockIdx.x - 256;
        int c0 = (b & 7) * 64, r0 = (b >> 3) * 64;
        int j = t & 63, i0 = t >> 6;     // i0: 0..7
#pragma unroll
        for (int k = 0; k < 8; k++) {
            int i = i0 + k * 8;
            tile[i][j] = Wv[(size_t)(r0 + i) * D + c0 + j];
        }
        __syncthreads();
#pragma unroll
        for (int k = 0; k < 8; k++) {
            int i = i0 + k * 8;
            float v = tile[j][i];                 // Wv[r0+j][c0+i]
            size_t o = (size_t)(c0 + i) * D + r0 + j;
            __nv_bfloat16 h = __float2bfloat16_rn(v);
            g_Bhi[o] = h;
            g_Blo[o] = __float2bfloat16_rn(v - __bfloat162float(h));
        }
    }
}

// ---------------------------------------------------------------------------
// k_gemm_mma: Vp = patch @ Wv + bv via mma.sync bf16 (2-term split, 3 products)
// CTA tile 128x64, 256 threads (4x2 warps, warp tile 32x32), K-chunk 32,
// cp.async 3-stage pipeline, 80B smem row pitch (conflict-free ldmatrix).
// Grid (8 n-tiles, 32 m-tiles) = 256 CTAs, 2 per SM.
// Epilogue also emits pf partials: g_pfp[bx][row] = tile_row . Wf.
// ---------------------------------------------------------------------------
#define A_BYTES  10240         // 128 rows * 80 B
#define B_BYTES  5120          // 64 rows * 80 B
#define OFF_ALO  10240
#define OFF_BHI  20480
#define OFF_BLO  25600
#define STAGE_B  30720
#define SMEM_MMA (3 * STAGE_B) // 92160

__global__ __launch_bounds__(256, 2) void k_gemm_mma(const float* __restrict__ bv,
                                                     const float* __restrict__ Wf) {
    extern __shared__ char sm[];
    uint32_t sbase = smem_u32(sm);
    int t = threadIdx.x, wid = t >> 5, lane = t & 31;
    int m0 = blockIdx.y * 128, n0 = blockIdx.x * 64;
    int wm = wid >> 1, wn = wid & 1;   // 4x2 warp grid, warp tile 32x32

    float acc[2][4][4];
#pragma unroll
    for (int i = 0; i < 2; i++)
#pragma unroll
        for (int j = 0; j < 4; j++)
#pragma unroll
            for (int k = 0; k < 4; k++) acc[i][j][k] = 0.f;

    int rowA[2], segA[2];
#pragma unroll
    for (int h = 0; h < 2; h++) {
        int rem = h * 256 + t;
        rowA[h] = rem >> 2; segA[h] = rem & 3;
    }
    int rowB = t >> 2, segB = t & 3;

    auto load_chunk = [&](int c) {
        int s = c % 3, k0 = c * 32;
        uint32_t base = sbase + s * STAGE_B;
#pragma unroll
        for (int h = 0; h < 2; h++) {
            int r = rowA[h], seg = segA[h];
            size_t go = (size_t)(m0 + r) * D + k0 + seg * 8;
            uint32_t so = (uint32_t)(r * 80 + seg * 16);
            cp16(base + so, g_Ahi + go);
            cp16(base + OFF_ALO + so, g_Alo + go);
        }
        {
            size_t go = (size_t)(n0 + rowB) * D + k0 + segB * 8;
            uint32_t so = (uint32_t)(rowB * 80 + segB * 16);
            cp16(base + OFF_BHI + so, g_Bhi + go);
            cp16(base + OFF_BLO + so, g_Blo + go);
        }
        CP_COMMIT();
    };

    uint32_t aoff = (uint32_t)((wm * 32 + (lane & 15)) * 80 + (lane >> 4) * 16);
    uint32_t boff = (uint32_t)((wn * 32 + (lane & 7) + ((lane >> 4) & 1) * 8) * 80
                               + ((lane >> 3) & 1) * 16);

    load_chunk(0);
    load_chunk(1);
    for (int c = 0; c < 16; c++) {
        if (c <= 13) { load_chunk(c + 2); CP_WAIT(2); }
        else if (c == 14) { CP_WAIT(1); }
        else { CP_WAIT(0); }
        __syncthreads();
        uint32_t st = sbase + (c % 3) * STAGE_B;
#pragma unroll
        for (int ks = 0; ks < 2; ks++) {
            uint32_t ah[2][4], al[2][4], bh[2][4], bl[2][4];
#pragma unroll
            for (int mt = 0; mt < 2; mt++) {
                ldm_x4(ah[mt], st + aoff + mt * (16 * 80) + ks * 32);
                ldm_x4(al[mt], st + OFF_ALO + aoff + mt * (16 * 80) + ks * 32);
            }
#pragma unroll
            for (int np = 0; np < 2; np++) {
                ldm_x4(bh[np], st + OFF_BHI + boff + np * (16 * 80) + ks * 32);
                ldm_x4(bl[np], st + OFF_BLO + boff + np * (16 * 80) + ks * 32);
            }
#pragma unroll
            for (int mt = 0; mt < 2; mt++)
#pragma unroll
                for (int np = 0; np < 2; np++) {
                    mma16816(acc[mt][2 * np],     ah[mt], &bh[np][0]);
                    mma16816(acc[mt][2 * np + 1], ah[mt], &bh[np][2]);
                    mma16816(acc[mt][2 * np],     ah[mt], &bl[np][0]);
                    mma16816(acc[mt][2 * np + 1], ah[mt], &bl[np][2]);
                    mma16816(acc[mt][2 * np],     al[mt], &bh[np][0]);
                    mma16816(acc[mt][2 * np + 1], al[mt], &bh[np][2]);
                }
        }
        __syncthreads();
    }

    // Epilogue: bias add, store Vp, pf partials (row . Wf over this 64-col tile)
    int g = lane >> 2, tig = lane & 3;
    float bcol0[4], bcol1[4], wcol0[4], wcol1[4];
#pragma unroll
    for (int nt = 0; nt < 4; nt++) {
        int col = n0 + wn * 32 + nt * 8 + tig * 2;
        bcol0[nt] = __ldg(bv + col); bcol1[nt] = __ldg(bv + col + 1);
        wcol0[nt] = __ldg(Wf + col); wcol1[nt] = __ldg(Wf + col + 1);
    }
    float* spf = reinterpret_cast<float*>(sm);  // [2][128], stages dead now
#pragma unroll
    for (int mt = 0; mt < 2; mt++) {
        int lr = wm * 32 + mt * 16 + g;
        int r = m0 + lr;
        float pf0 = 0.f, pf1 = 0.f;
#pragma unroll
        for (int nt = 0; nt < 4; nt++) {
            int col = n0 + wn * 32 + nt * 8 + tig * 2;
            float2 v0 = make_float2(acc[mt][nt][0] + bcol0[nt], acc[mt][nt][1] + bcol1[nt]);
            float2 v1 = make_float2(acc[mt][nt][2] + bcol0[nt], acc[mt][nt][3] + bcol1[nt]);
            *reinterpret_cast<float2*>(&g_Vp[(size_t)r * D + col]) = v0;
            *reinterpret_cast<float2*>(&g_Vp[(size_t)(r + 8) * D + col]) = v1;
            pf0 += v0.x * wcol0[nt] + v0.y * wcol1[nt];
            pf1 += v1.x * wcol0[nt] + v1.y * wcol1[nt];
        }
        pf0 += __shfl_xor_sync(0xffffffffu, pf0, 1);
        pf0 += __shfl_xor_sync(0xffffffffu, pf0, 2);
        pf1 += __shfl_xor_sync(0xffffffffu, pf1, 1);
        pf1 += __shfl_xor_sync(0xffffffffu, pf1, 2);
        if (tig == 0) {
            spf[wn * 128 + lr] = pf0;
            spf[wn * 128 + lr + 8] = pf1;
        }
    }
    __syncthreads();
    if (t < 128) {
        g_pfp[blockIdx.x][m0 + t] = spf[t] + spf[128 + t];
    }
}

// ---------------------------------------------------------------------------
// k_combine: one block per group n. Collapsed form:
//  out[d] = sum_q c0[q]*VQ[q,d] + sum_p e[p]*Vp[idx_p,d]
// ---------------------------------------------------------------------------
__global__ __launch_bounds__(128) void k_combine(const int* __restrict__ indices,
                                                 const unsigned* __restrict__ mask,
                                                 const float* __restrict__ bf,
                                                 float* __restrict__ out) {
    __shared__ float S[QN][72];
    __shared__ int sidx[PP];
    __shared__ unsigned smk[PP];
    __shared__ float pfs[PP];
    __shared__ float tqs[QN];
    __shared__ float invq[QN];
    __shared__ float fq[QN];
    __shared__ float es[PP];
    int n = blockIdx.x, t = threadIdx.x;
    int lane = t & 31, w = t >> 5;
    const float NINF = __int_as_float(0xff800000u);

    if (t < PP) {
        sidx[t] = indices[n * PP + t];
        smk[t]  = mask[n * PP + t];
    }
    if (t < QN) tqs[t] = g_tq[t];
    __syncthreads();

    {
        int p = t & 63, half = t >> 6;
        int idx = sidx[p];
        float4 v0, v1;
        if (smk[p] != 0u) {
            const float4* sp4 = reinterpret_cast<const float4*>(g_sp + (size_t)idx * QN + half * 8);
            v0 = sp4[0]; v1 = sp4[1];
        } else {
            v0 = make_float4(NINF, NINF, NINF, NINF);
            v1 = v0;
        }
        int q0 = half * 8;
        S[q0 + 0][p + 1] = v0.x; S[q0 + 1][p + 1] = v0.y;
        S[q0 + 2][p + 1] = v0.z; S[q0 + 3][p + 1] = v0.w;
        S[q0 + 4][p + 1] = v1.x; S[q0 + 5][p + 1] = v1.y;
        S[q0 + 6][p + 1] = v1.z; S[q0 + 7][p + 1] = v1.w;
        if (t < PP) {
            int idx2 = sidx[t];
            float s = 0.f;
#pragma unroll
            for (int b = 0; b < 8; b++) s += g_pfp[b][idx2];
            pfs[t] = s;
        }
    }
    if (t < QN) S[t][0] = g_sself[t];
    __syncthreads();

    {
        float bf0 = bf[0];
#pragma unroll
        for (int qi = 0; qi < 4; qi++) {
            int q = w * 4 + qi;
            float v0 = S[q][lane], v1 = S[q][lane + 32];
            float v2 = (lane == 0) ? S[q][64] : NINF;
            float mx = fmaxf(fmaxf(v0, v1), v2);
#pragma unroll
            for (int o = 16; o; o >>= 1) mx = fmaxf(mx, __shfl_xor_sync(0xffffffffu, mx, o));
            float e0 = expf(v0 - mx), e1 = expf(v1 - mx);
            float e2 = (lane == 0) ? expf(v2 - mx) : 0.f;
            float s = e0 + e1 + e2;
#pragma unroll
            for (int o = 16; o; o >>= 1) s += __shfl_xor_sync(0xffffffffu, s, o);
            S[q][lane] = e0; S[q][lane + 32] = e1;
            if (lane == 0) S[q][64] = e2;
            float pr0 = (lane == 0) ? tqs[q] : pfs[lane - 1];
            float fp = e0 * pr0 + e1 * pfs[lane + 31];
            if (lane == 0) fp += e2 * pfs[63];
#pragma unroll
            for (int o = 16; o; o >>= 1) fp += __shfl_xor_sync(0xffffffffu, fp, o);
            if (lane == 0) {
                invq[q] = 1.f / s;
                fq[q] = fp / s + bf0;
            }
        }
    }
    __syncthreads();

    float c[QN];
    {
        float fv[QN], mx = -3.4e38f;
#pragma unroll
        for (int q = 0; q < QN; q++) { fv[q] = fq[q]; mx = fmaxf(mx, fv[q]); }
        float s = 0.f;
#pragma unroll
        for (int q = 0; q < QN; q++) { fv[q] = expf(fv[q] - mx); s += fv[q]; }
        float inv = 1.f / s;
#pragma unroll
        for (int q = 0; q < QN; q++) c[q] = fv[q] * inv * invq[q];
    }

    if (t < PP) {
        float ep = 0.f;
#pragma unroll
        for (int q = 0; q < QN; q++) ep += c[q] * S[q][t + 1];
        es[t] = ep;
    }
    __syncthreads();

    float4 o = make_float4(0.f, 0.f, 0.f, 0.f);
    {
        const float4* VQ4 = reinterpret_cast<const float4*>(g_VQ);
#pragma unroll
        for (int q = 0; q < QN; q++) {
            float c0 = c[q] * S[q][0];
            float4 vq = VQ4[q * 128 + t];
            o.x += c0 * vq.x; o.y += c0 * vq.y;
            o.z += c0 * vq.z; o.w += c0 * vq.w;
        }
    }
    const float4* Vp4 = reinterpret_cast<const float4*>(g_Vp);
#pragma unroll 8
    for (int p = 0; p < PP; p++) {
        float ep = es[p];
        if (ep != 0.f) {
            float4 v = Vp4[(size_t)sidx[p] * 128 + t];
            o.x += ep * v.x; o.y += ep * v.y;
            o.z += ep * v.z; o.w += ep * v.w;
        }
    }
    reinterpret_cast<float4*>(out)[(size_t)n * 128 + t] = o;
}

// ---------------------------------------------------------------------------
extern "C" void kernel_launch(void* const* d_in, const int* in_sizes, int n_in,
                              void* d_out, int out_size) {
    (void)in_sizes; (void)n_in; (void)out_size;
    const float* patch   = (const float*)d_in[0];
    const float* query   = (const float*)d_in[1];
    const float* Wk      = (const float*)d_in[2];
    const float* bk      = (const float*)d_in[3];
    const float* Wv      = (const float*)d_in[4];
    const float* bv      = (const float*)d_in[5];
    const float* Wf      = (const float*)d_in[6];
    const float* bf      = (const float*)d_in[7];
    const int* indices   = (const int*)d_in[8];
    const unsigned* mask = (const unsigned*)d_in[9];
    float* out           = (float*)d_out;

    cudaFuncSetAttribute(k_gemm_mma, cudaFuncAttributeMaxDynamicSharedMemorySize, SMEM_MMA);

    k_pre<<<dim3(QN, 2), D>>>(query, Wk, Wv, bv, bk, Wf);
    k_sp<<<256 + 64, 512>>>(patch, Wv);
    k_gemm_mma<<<dim3(8, 32), 256, SMEM_MMA>>>(bv, Wf);
    k_combine<<<NG, 128>>>(indices, mask, bf, out);
}